// round 3
// baseline (speedup 1.0000x reference)
#include <cuda_runtime.h>
#include <cuda_fp16.h>
#include <stdint.h>

#define DIM    5120
#define SQ     16384
#define KVLEN  257
#define KVP    288
#define NHEADS 40
#define HDIM   128

// ---------------- scratch (device globals; no allocs allowed) ----------------
__device__ __half g_Hh  [(size_t)SQ * DIM];
__device__ __half g_Eh  [(size_t)KVLEN * DIM];
__device__ __half g_Wqh [(size_t)DIM * DIM];
__device__ __half g_Wkh [(size_t)DIM * DIM];
__device__ __half g_Wvh [(size_t)DIM * DIM];
__device__ float  g_Qraw[(size_t)SQ * DIM];
__device__ float  g_Kraw[(size_t)KVLEN * DIM];
__device__ __half g_Qh  [(size_t)SQ * DIM];
__device__ __half g_Kh  [(size_t)KVP * DIM];   // rows >= 257 stay zero
__device__ __half g_Vh  [(size_t)KVP * DIM];   // rows >= 257 stay zero
__device__ float  g_ssq_q[SQ];
__device__ float  g_ssq_k[KVLEN];

// ---------------- helpers ----------------
__device__ __forceinline__ uint32_t smem_u32(const void* p) {
    return (uint32_t)__cvta_generic_to_shared(p);
}

__device__ __forceinline__ void ldmx4(uint32_t& r0, uint32_t& r1, uint32_t& r2, uint32_t& r3,
                                      const __half* p) {
    asm volatile("ldmatrix.sync.aligned.m8n8.x4.shared.b16 {%0,%1,%2,%3}, [%4];"
                 : "=r"(r0), "=r"(r1), "=r"(r2), "=r"(r3)
                 : "r"(smem_u32(p)));
}

__device__ __forceinline__ void ldmx4t(uint32_t& r0, uint32_t& r1, uint32_t& r2, uint32_t& r3,
                                       const __half* p) {
    asm volatile("ldmatrix.sync.aligned.m8n8.x4.trans.shared.b16 {%0,%1,%2,%3}, [%4];"
                 : "=r"(r0), "=r"(r1), "=r"(r2), "=r"(r3)
                 : "r"(smem_u32(p)));
}

__device__ __forceinline__ void mma16816(float* c, const uint32_t* a, const uint32_t* b) {
    asm volatile(
        "mma.sync.aligned.m16n8k16.row.col.f32.f16.f16.f32 "
        "{%0,%1,%2,%3},{%4,%5,%6,%7},{%8,%9},{%0,%1,%2,%3};"
        : "+f"(c[0]), "+f"(c[1]), "+f"(c[2]), "+f"(c[3])
        : "r"(a[0]), "r"(a[1]), "r"(a[2]), "r"(a[3]), "r"(b[0]), "r"(b[1]));
}

__device__ __forceinline__ void cp16(uint32_t dst, const void* src, bool pred) {
    asm volatile("cp.async.cg.shared.global [%0], [%1], 16, %2;"
                 :: "r"(dst), "l"(src), "r"(pred ? 16 : 0) : "memory");
}
#define CP_COMMIT() asm volatile("cp.async.commit_group;" ::: "memory")
#define CP_WAIT2()  asm volatile("cp.async.wait_group 2;" ::: "memory")

// ---------------- small utility kernels ----------------
__global__ void k_f2h(const float* __restrict__ src, __half* __restrict__ dst, int n) {
    int i0 = blockIdx.x * blockDim.x + threadIdx.x;
    int st = gridDim.x * blockDim.x;
    int n2 = n >> 1;
    for (int i = i0; i < n2; i += st) {
        float2 v = ((const float2*)src)[i];
        ((__half2*)dst)[i] = __floats2half2_rn(v.x, v.y);
    }
}

__global__ void k_zero(float* __restrict__ p, int n) {
    int i0 = blockIdx.x * blockDim.x + threadIdx.x;
    int st = gridDim.x * blockDim.x;
    for (int i = i0; i < n; i += st) p[i] = 0.f;
}

__global__ void k_norm(const float* __restrict__ raw, const float* __restrict__ ssq,
                       const float* __restrict__ g, __half* __restrict__ o, int M) {
    int i0 = blockIdx.x * blockDim.x + threadIdx.x;
    int st = gridDim.x * blockDim.x;
    int n = M * DIM;
    for (int i = i0; i < n; i += st) {
        int r = i / DIM;
        int c = i - r * DIM;
        float sc = rsqrtf(ssq[r] * (1.0f / DIM) + 1e-6f);
        o[i] = __float2half(raw[i] * sc * g[c]);
    }
}

// ---------------- projection GEMM: out[m,n] = sum_k A[m,k]*W[n,k] + bias[n] ----------------
// BM=128, BN=256, BK=32; 8 warps (2m x 4n), warp tile 64x64.
// 4-stage cp.async pipeline, one __syncthreads per stage.
// mode 0: write fp32 raw + atomic per-row sum of squares; mode 1: write fp16 (V path).
#define GBM 128
#define GBN 256
#define GBK 32
#define GPAD 40                         // halves per row in smem (32 data + 8 pad)
#define G_A_HALVES (GBM * GPAD)         // 5120 halves = 10240 B
#define G_B_HALVES (GBN * GPAD)         // 10240 halves = 20480 B
#define G_STAGE_HALVES (G_A_HALVES + G_B_HALVES)
#define G_STAGES 4
#define G_SMEM (G_STAGES * G_STAGE_HALVES * 2 + GBN * 4)
#define G_NIT (DIM / GBK)               // 160

__global__ __launch_bounds__(256, 1)
void k_gemm(const __half* __restrict__ A, const __half* __restrict__ W,
            const float* __restrict__ bias, int M,
            float* __restrict__ rawOut, __half* __restrict__ hOut,
            float* __restrict__ ssq, int mode) {
    extern __shared__ __align__(16) char sm_raw[];
    __half* smh = (__half*)sm_raw;
    float* sBias = (float*)(sm_raw + G_STAGES * G_STAGE_HALVES * 2);

    const int tid = threadIdx.x, lane = tid & 31, wid = tid >> 5;
    const int wm = wid >> 2, wn = wid & 3;          // 2m x 4n warps
    const int m0 = blockIdx.y * GBM, n0 = blockIdx.x * GBN;

    sBias[tid] = bias[n0 + tid];

    // ---- stage loader: A 512 chunks + B 1024 chunks of 16B; 6 per thread ----
    auto load_stage = [&](int s) {
        const int kk = s * GBK;
        __half* st = smh + (s & (G_STAGES - 1)) * G_STAGE_HALVES;
        // A: chunks tid, tid+256
#pragma unroll
        for (int j = 0; j < 2; j++) {
            int ch = tid + j * 256;
            int r = ch >> 2, c16 = ch & 3;
            int row = m0 + r;
            bool ok = row < M;
            const __half* src = A + (size_t)(ok ? row : 0) * DIM + kk + c16 * 8;
            cp16(smem_u32(&st[r * GPAD + c16 * 8]), src, ok);
        }
        // B: chunks tid + 256*j, j<4
        __half* bt = st + G_A_HALVES;
#pragma unroll
        for (int j = 0; j < 4; j++) {
            int ch = tid + j * 256;
            int r = ch >> 2, c16 = ch & 3;
            const __half* src = W + (size_t)(n0 + r) * DIM + kk + c16 * 8;
            cp16(smem_u32(&bt[r * GPAD + c16 * 8]), src, true);
        }
        CP_COMMIT();
    };

    float acc[4][8][4];
#pragma unroll
    for (int i = 0; i < 4; i++)
#pragma unroll
        for (int j = 0; j < 8; j++)
#pragma unroll
            for (int k = 0; k < 4; k++) acc[i][j][k] = 0.f;

    // prologue: 3 stages in flight
    load_stage(0);
    load_stage(1);
    load_stage(2);

    for (int i = 0; i < G_NIT; i++) {
        CP_WAIT2();          // stage i resident (3 groups outstanding before wait)
        __syncthreads();     // all warps done with buffer (i-1)%4 == (i+3)%4
        if (i + 3 < G_NIT) load_stage(i + 3);
        else CP_COMMIT();    // empty group keeps the wait_group count uniform

        const __half* a_s = smh + (i & (G_STAGES - 1)) * G_STAGE_HALVES;
        const __half* b_s = a_s + G_A_HALVES;

#pragma unroll
        for (int ks = 0; ks < GBK; ks += 16) {
            uint32_t af[4][4];
#pragma unroll
            for (int mf = 0; mf < 4; mf++) {
                int mr = wm * 64 + mf * 16 + (lane & 7) + ((lane >> 3) & 1) * 8;
                int mc = ks + (lane >> 4) * 8;
                ldmx4(af[mf][0], af[mf][1], af[mf][2], af[mf][3], &a_s[mr * GPAD + mc]);
            }
            uint32_t bf[8][2];
#pragma unroll
            for (int np = 0; np < 4; np++) {
                int nr = wn * 64 + np * 16 + (lane & 7) + ((lane >> 4) ? 8 : 0);
                int nc = ks + (((lane >> 3) & 1) ? 8 : 0);
                ldmx4(bf[2 * np][0], bf[2 * np][1], bf[2 * np + 1][0], bf[2 * np + 1][1],
                      &b_s[nr * GPAD + nc]);
            }
#pragma unroll
            for (int mf = 0; mf < 4; mf++)
#pragma unroll
                for (int nf = 0; nf < 8; nf++) mma16816(acc[mf][nf], af[mf], bf[nf]);
        }
    }

    // epilogue
#pragma unroll
    for (int mf = 0; mf < 4; mf++) {
#pragma unroll
        for (int rh = 0; rh < 2; rh++) {
            int gr = m0 + wm * 64 + mf * 16 + (lane >> 2) + rh * 8;
            if (gr >= M) continue;
            float s = 0.f;
#pragma unroll
            for (int nf = 0; nf < 8; nf++) {
                int lc = wn * 64 + nf * 8 + 2 * (lane & 3);
                float v0 = acc[mf][nf][rh * 2 + 0] + sBias[lc];
                float v1 = acc[mf][nf][rh * 2 + 1] + sBias[lc + 1];
                if (mode == 0) {
                    *(float2*)&rawOut[(size_t)gr * DIM + n0 + lc] = make_float2(v0, v1);
                    s += v0 * v0 + v1 * v1;
                } else {
                    *(__half2*)&hOut[(size_t)gr * DIM + n0 + lc] = __floats2half2_rn(v0, v1);
                }
            }
            if (mode == 0) atomicAdd(&ssq[gr], s);
        }
    }
}

// ---------------- fused attention ----------------
#define QK_STRIDE 136
#define PS_STRIDE 296
#define SMEM_QS   0
#define SMEM_KS   34816
#define SMEM_PS   (34816 + 78336)
#define SMEM_RS   (34816 + 78336 + 75776)
#define ATTN_SMEM (34816 + 78336 + 75776 + 512)

__global__ __launch_bounds__(256, 1)
void k_attn(float* __restrict__ out) {
    extern __shared__ __align__(16) char smem[];
    __half* Qs = (__half*)(smem + SMEM_QS);
    __half* Ks = (__half*)(smem + SMEM_KS);  // reused for V in phase 2
    __half* Ps = (__half*)(smem + SMEM_PS);
    float* rowsum = (float*)(smem + SMEM_RS);

    const int tid = threadIdx.x, lane = tid & 31, wid = tid >> 5;
    const int wm = wid & 3, wn = wid >> 2;
    const int m0 = blockIdx.x * 128;
    const int h = blockIdx.y;
    const size_t hc = (size_t)h * HDIM;

    if (tid < 128) rowsum[tid] = 0.f;
#pragma unroll
    for (int i = 0; i < 8; i++) {
        int idx = tid + 256 * i;
        int r = idx >> 4, c = (idx & 15) * 8;
        *(uint4*)&Qs[r * QK_STRIDE + c] = *(const uint4*)&g_Qh[(size_t)(m0 + r) * DIM + hc + c];
    }
#pragma unroll
    for (int i = 0; i < 18; i++) {
        int idx = tid + 256 * i;
        int r = idx >> 4, c = (idx & 15) * 8;
        *(uint4*)&Ks[r * QK_STRIDE + c] = *(const uint4*)&g_Kh[(size_t)r * DIM + hc + c];
    }
    __syncthreads();

    const float SCALE = 0.088388347648318447f;  // 1/sqrt(128)
    for (int p = 0; p < 3; p++) {
        float acc[2][6][4];
#pragma unroll
        for (int i = 0; i < 2; i++)
#pragma unroll
            for (int j = 0; j < 6; j++)
#pragma unroll
                for (int k = 0; k < 4; k++) acc[i][j][k] = 0.f;

#pragma unroll
        for (int kk = 0; kk < 8; kk++) {
            int ks = kk * 16;
            uint32_t af[2][4];
#pragma unroll
            for (int mf = 0; mf < 2; mf++) {
                int mr = wm * 32 + mf * 16 + (lane & 7) + ((lane >> 3) & 1) * 8;
                int mc = ks + (lane >> 4) * 8;
                ldmx4(af[mf][0], af[mf][1], af[mf][2], af[mf][3], &Qs[mr * QK_STRIDE + mc]);
            }
            uint32_t bf[6][2];
#pragma unroll
            for (int np = 0; np < 3; np++) {
                int nr = p * 96 + wn * 48 + np * 16 + (lane & 7) + ((lane >> 4) ? 8 : 0);
                int nc = ks + (((lane >> 3) & 1) ? 8 : 0);
                ldmx4(bf[2 * np][0], bf[2 * np][1], bf[2 * np + 1][0], bf[2 * np + 1][1],
                      &Ks[nr * QK_STRIDE + nc]);
            }
#pragma unroll
            for (int mf = 0; mf < 2; mf++)
#pragma unroll
                for (int nf = 0; nf < 6; nf++) mma16816(acc[mf][nf], af[mf], bf[nf]);
        }
#pragma unroll
        for (int mf = 0; mf < 2; mf++) {
#pragma unroll
            for (int rh = 0; rh < 2; rh++) {
                int r = wm * 32 + mf * 16 + (lane >> 2) + rh * 8;
                float s = 0.f;
#pragma unroll
                for (int nf = 0; nf < 6; nf++) {
                    int col = p * 96 + wn * 48 + nf * 8 + 2 * (lane & 3);
                    float v0 = (col < KVLEN) ? __expf(acc[mf][nf][rh * 2 + 0] * SCALE) : 0.f;
                    float v1 = (col + 1 < KVLEN) ? __expf(acc[mf][nf][rh * 2 + 1] * SCALE) : 0.f;
                    *(__half2*)&Ps[r * PS_STRIDE + col] = __floats2half2_rn(v0, v1);
                    s += v0 + v1;
                }
                atomicAdd(&rowsum[r], s);
            }
        }
    }
    __syncthreads();
#pragma unroll
    for (int i = 0; i < 18; i++) {
        int idx = tid + 256 * i;
        int r = idx >> 4, c = (idx & 15) * 8;
        *(uint4*)&Ks[r * QK_STRIDE + c] = *(const uint4*)&g_Vh[(size_t)r * DIM + hc + c];
    }
    __syncthreads();

    float oc[2][8][4];
#pragma unroll
    for (int i = 0; i < 2; i++)
#pragma unroll
        for (int j = 0; j < 8; j++)
#pragma unroll
            for (int k = 0; k < 4; k++) oc[i][j][k] = 0.f;

    for (int kk = 0; kk < 18; kk++) {
        int ks = kk * 16;
        uint32_t af[2][4];
#pragma unroll
        for (int mf = 0; mf < 2; mf++) {
            int mr = wm * 32 + mf * 16 + (lane & 7) + ((lane >> 3) & 1) * 8;
            int mc = ks + (lane >> 4) * 8;
            ldmx4(af[mf][0], af[mf][1], af[mf][2], af[mf][3], &Ps[mr * PS_STRIDE + mc]);
        }
        uint32_t bf[8][2];
#pragma unroll
        for (int np = 0; np < 4; np++) {
            int vr = ks + (lane & 7) + ((lane >> 3) & 1) * 8;
            int vc = wn * 64 + np * 16 + (lane >> 4) * 8;
            ldmx4t(bf[2 * np][0], bf[2 * np][1], bf[2 * np + 1][0], bf[2 * np + 1][1],
                   &Ks[vr * QK_STRIDE + vc]);
        }
#pragma unroll
        for (int mf = 0; mf < 2; mf++)
#pragma unroll
            for (int nf = 0; nf < 8; nf++) mma16816(oc[mf][nf], af[mf], bf[nf]);
    }

#pragma unroll
    for (int mf = 0; mf < 2; mf++) {
#pragma unroll
        for (int rh = 0; rh < 2; rh++) {
            int r = wm * 32 + mf * 16 + (lane >> 2) + rh * 8;
            float inv = 1.0f / rowsum[r];
            size_t gro = (size_t)(m0 + r) * DIM + hc;
#pragma unroll
            for (int nf = 0; nf < 8; nf++) {
                int c = wn * 64 + nf * 8 + 2 * (lane & 3);
                *(float2*)&out[gro + c] =
                    make_float2(oc[mf][nf][rh * 2 + 0] * inv, oc[mf][nf][rh * 2 + 1] * inv);
            }
        }
    }
}

// ---------------- launcher ----------------
extern "C" void kernel_launch(void* const* d_in, const int* in_sizes, int n_in,
                              void* d_out, int out_size) {
    const float* hidden = (const float*)d_in[0];
    const float* enc = (const float*)d_in[1];
    const float* wq = (const float*)d_in[2];
    const float* bq = (const float*)d_in[3];
    const float* wk = (const float*)d_in[4];
    const float* bk = (const float*)d_in[5];
    const float* wv = (const float*)d_in[6];
    const float* bv = (const float*)d_in[7];
    const float* gq = (const float*)d_in[8];
    const float* gk = (const float*)d_in[9];
    float* out = (float*)d_out;

    void* p;
    cudaGetSymbolAddress(&p, g_Hh);    __half* Hh = (__half*)p;
    cudaGetSymbolAddress(&p, g_Eh);    __half* Eh = (__half*)p;
    cudaGetSymbolAddress(&p, g_Wqh);   __half* Wqh = (__half*)p;
    cudaGetSymbolAddress(&p, g_Wkh);   __half* Wkh = (__half*)p;
    cudaGetSymbolAddress(&p, g_Wvh);   __half* Wvh = (__half*)p;
    cudaGetSymbolAddress(&p, g_Qraw);  float* Qraw = (float*)p;
    cudaGetSymbolAddress(&p, g_Kraw);  float* Kraw = (float*)p;
    cudaGetSymbolAddress(&p, g_Qh);    __half* Qh = (__half*)p;
    cudaGetSymbolAddress(&p, g_Kh);    __half* Kh = (__half*)p;
    cudaGetSymbolAddress(&p, g_Vh);    __half* Vh = (__half*)p;
    cudaGetSymbolAddress(&p, g_ssq_q); float* ssq_q = (float*)p;
    cudaGetSymbolAddress(&p, g_ssq_k); float* ssq_k = (float*)p;

    // fp32 -> fp16 conversions
    k_f2h<<<2048, 256>>>(hidden, Hh, SQ * DIM);
    k_f2h<<<1024, 256>>>(wq, Wqh, DIM * DIM);
    k_f2h<<<1024, 256>>>(wk, Wkh, DIM * DIM);
    k_f2h<<<1024, 256>>>(wv, Wvh, DIM * DIM);
    k_f2h<<<128, 256>>>(enc, Eh, KVLEN * DIM);
    k_zero<<<64, 256>>>(ssq_q, SQ);
    k_zero<<<2, 256>>>(ssq_k, KVLEN);

    // projections
    cudaFuncSetAttribute(k_gemm, cudaFuncAttributeMaxDynamicSharedMemorySize, G_SMEM);
    k_gemm<<<dim3(20, 128), 256, G_SMEM>>>(Hh, Wqh, bq, SQ, Qraw, ((__half*)0), ssq_q, 0);
    k_gemm<<<dim3(20, 3), 256, G_SMEM>>>(Eh, Wkh, bk, KVLEN, Kraw, ((__half*)0), ssq_k, 0);
    k_gemm<<<dim3(20, 3), 256, G_SMEM>>>(Eh, Wvh, bv, KVLEN, ((float*)0), Vh, ((float*)0), 1);

    // rmsnorm -> fp16
    k_norm<<<2048, 256>>>(Qraw, ssq_q, gq, Qh, SQ);
    k_norm<<<64, 256>>>(Kraw, ssq_k, gk, Kh, KVLEN);

    // attention
    cudaFuncSetAttribute(k_attn, cudaFuncAttributeMaxDynamicSharedMemorySize, ATTN_SMEM);
    k_attn<<<dim3(128, NHEADS), 256, ATTN_SMEM>>>(out);
}

// round 4
// speedup vs baseline: 1.0262x; 1.0262x over previous
#include <cuda_runtime.h>
#include <cuda_fp16.h>
#include <stdint.h>

#define DIM    5120
#define SQ     16384
#define KVLEN  257
#define KVP    288
#define NHEADS 40
#define HDIM   128

// ---------------- scratch (device globals; no allocs allowed) ----------------
__device__ __half g_Hh  [(size_t)SQ * DIM];
__device__ __half g_Eh  [(size_t)KVLEN * DIM];
__device__ __half g_Wqh [(size_t)DIM * DIM];
__device__ __half g_Wkh [(size_t)DIM * DIM];
__device__ __half g_Wvh [(size_t)DIM * DIM];
__device__ float  g_Qraw[(size_t)SQ * DIM];
__device__ float  g_Kraw[(size_t)KVLEN * DIM];
__device__ __half g_Qh  [(size_t)SQ * DIM];
__device__ __half g_Kh  [(size_t)KVP * DIM];   // rows >= 257 stay zero (static zero-init)
__device__ __half g_Vh  [(size_t)KVP * DIM];   // rows >= 257 stay zero

// ---------------- helpers ----------------
__device__ __forceinline__ uint32_t smem_u32(const void* p) {
    return (uint32_t)__cvta_generic_to_shared(p);
}

__device__ __forceinline__ void ldmx4(uint32_t& r0, uint32_t& r1, uint32_t& r2, uint32_t& r3,
                                      const __half* p) {
    asm volatile("ldmatrix.sync.aligned.m8n8.x4.shared.b16 {%0,%1,%2,%3}, [%4];"
                 : "=r"(r0), "=r"(r1), "=r"(r2), "=r"(r3)
                 : "r"(smem_u32(p)));
}

__device__ __forceinline__ void ldmx4t(uint32_t& r0, uint32_t& r1, uint32_t& r2, uint32_t& r3,
                                       const __half* p) {
    asm volatile("ldmatrix.sync.aligned.m8n8.x4.trans.shared.b16 {%0,%1,%2,%3}, [%4];"
                 : "=r"(r0), "=r"(r1), "=r"(r2), "=r"(r3)
                 : "r"(smem_u32(p)));
}

__device__ __forceinline__ void mma16816(float* c, const uint32_t* a, const uint32_t* b) {
    asm volatile(
        "mma.sync.aligned.m16n8k16.row.col.f32.f16.f16.f32 "
        "{%0,%1,%2,%3},{%4,%5,%6,%7},{%8,%9},{%0,%1,%2,%3};"
        : "+f"(c[0]), "+f"(c[1]), "+f"(c[2]), "+f"(c[3])
        : "r"(a[0]), "r"(a[1]), "r"(a[2]), "r"(a[3]), "r"(b[0]), "r"(b[1]));
}

__device__ __forceinline__ void cp16(uint32_t dst, const void* src, bool pred) {
    asm volatile("cp.async.cg.shared.global [%0], [%1], 16, %2;"
                 :: "r"(dst), "l"(src), "r"(pred ? 16 : 0) : "memory");
}
#define CP_COMMIT() asm volatile("cp.async.commit_group;" ::: "memory")
#define CP_WAIT2()  asm volatile("cp.async.wait_group 2;" ::: "memory")

// ---------------- small utility kernels ----------------
__global__ void k_f2h(const float* __restrict__ src, __half* __restrict__ dst, int n) {
    int i0 = blockIdx.x * blockDim.x + threadIdx.x;
    int st = gridDim.x * blockDim.x;
    int n2 = n >> 1;
    for (int i = i0; i < n2; i += st) {
        float2 v = ((const float2*)src)[i];
        ((__half2*)dst)[i] = __floats2half2_rn(v.x, v.y);
    }
}

// block-per-row rmsnorm: reduce ssq in-block, normalize, write fp16
__global__ __launch_bounds__(256)
void k_norm(const float* __restrict__ raw, const float* __restrict__ g,
            __half* __restrict__ o, int M) {
    int r = blockIdx.x;
    if (r >= M) return;
    const float4* row = (const float4*)(raw + (size_t)r * DIM);
    float4 v[5];
    float s = 0.f;
#pragma unroll
    for (int j = 0; j < 5; j++) {
        v[j] = row[threadIdx.x + j * 256];
        s += v[j].x * v[j].x + v[j].y * v[j].y + v[j].z * v[j].z + v[j].w * v[j].w;
    }
#pragma unroll
    for (int off = 16; off; off >>= 1) s += __shfl_xor_sync(0xffffffffu, s, off);
    __shared__ float ws[8];
    int lane = threadIdx.x & 31, wid = threadIdx.x >> 5;
    if (lane == 0) ws[wid] = s;
    __syncthreads();
    float tot = ws[0] + ws[1] + ws[2] + ws[3] + ws[4] + ws[5] + ws[6] + ws[7];
    float sc = rsqrtf(tot * (1.f / DIM) + 1e-6f);
    const float4* gp = (const float4*)g;
    __half2* op = (__half2*)(o + (size_t)r * DIM);
#pragma unroll
    for (int j = 0; j < 5; j++) {
        int ci = threadIdx.x + j * 256;
        float4 gg = gp[ci];
        op[ci * 2 + 0] = __floats2half2_rn(v[j].x * sc * gg.x, v[j].y * sc * gg.y);
        op[ci * 2 + 1] = __floats2half2_rn(v[j].z * sc * gg.z, v[j].w * sc * gg.w);
    }
}

// ---------------- Q projection GEMM (big): out = A*W^T + bias, fp32 raw ----------------
// 512 threads, BM=128, BN=256, BK=32; 16 warps (4m x 4n), warp tile 32x64.
// 4-stage cp.async pipeline. M assumed multiple of 128 (SQ=16384).
#define GBM 128
#define GBN 256
#define GBK 32
#define GPAD 40
#define G_A_HALVES (GBM * GPAD)   // 5120
#define G_B_HALVES (GBN * GPAD)   // 10240
#define G_STAGE    (G_A_HALVES + G_B_HALVES)  // 15360 halves = 30720 B
#define G_STAGES   4
#define G_SMEM     (G_STAGES * G_STAGE * 2 + GBN * 4)
#define G_NIT      (DIM / GBK)    // 160

__global__ __launch_bounds__(512, 1)
void k_gemm_q(const __half* __restrict__ A, const __half* __restrict__ W,
              const float* __restrict__ bias, float* __restrict__ out) {
    extern __shared__ __align__(16) char sm_raw[];
    __half* smh = (__half*)sm_raw;
    float* sBias = (float*)(sm_raw + G_STAGES * G_STAGE * 2);

    const int tid = threadIdx.x, lane = tid & 31, wid = tid >> 5;
    const int wm = wid >> 2, wn = wid & 3;  // 4m x 4n
    const int m0 = blockIdx.y * GBM, n0 = blockIdx.x * GBN;

    if (tid < 256) sBias[tid] = bias[n0 + tid];

    auto load_stage = [&](int s) {
        const int kk = s * GBK;
        __half* st = smh + (s & (G_STAGES - 1)) * G_STAGE;
        {   // A: 512 chunks of 16B, one per thread
            int r = tid >> 2, c16 = tid & 3;
            cp16(smem_u32(&st[r * GPAD + c16 * 8]),
                 A + (size_t)(m0 + r) * DIM + kk + c16 * 8, true);
        }
        __half* bt = st + G_A_HALVES;
#pragma unroll
        for (int j = 0; j < 2; j++) {  // B: 1024 chunks, two per thread
            int ch = tid + j * 512;
            int r = ch >> 2, c16 = ch & 3;
            cp16(smem_u32(&bt[r * GPAD + c16 * 8]),
                 W + (size_t)(n0 + r) * DIM + kk + c16 * 8, true);
        }
        CP_COMMIT();
    };

    float acc[2][8][4];
#pragma unroll
    for (int i = 0; i < 2; i++)
#pragma unroll
        for (int j = 0; j < 8; j++)
#pragma unroll
            for (int k = 0; k < 4; k++) acc[i][j][k] = 0.f;

    load_stage(0);
    load_stage(1);
    load_stage(2);

    for (int i = 0; i < G_NIT; i++) {
        CP_WAIT2();
        __syncthreads();
        if (i + 3 < G_NIT) load_stage(i + 3);
        else CP_COMMIT();

        const __half* a_s = smh + (i & (G_STAGES - 1)) * G_STAGE;
        const __half* b_s = a_s + G_A_HALVES;

#pragma unroll
        for (int ks = 0; ks < GBK; ks += 16) {
            uint32_t af[2][4];
#pragma unroll
            for (int mf = 0; mf < 2; mf++) {
                int mr = wm * 32 + mf * 16 + (lane & 7) + ((lane >> 3) & 1) * 8;
                int mc = ks + (lane >> 4) * 8;
                ldmx4(af[mf][0], af[mf][1], af[mf][2], af[mf][3], &a_s[mr * GPAD + mc]);
            }
            uint32_t bf[8][2];
#pragma unroll
            for (int np = 0; np < 4; np++) {
                int nr = wn * 64 + np * 16 + (lane & 7) + ((lane >> 4) ? 8 : 0);
                int nc = ks + (((lane >> 3) & 1) ? 8 : 0);
                ldmx4(bf[2 * np][0], bf[2 * np][1], bf[2 * np + 1][0], bf[2 * np + 1][1],
                      &b_s[nr * GPAD + nc]);
            }
#pragma unroll
            for (int mf = 0; mf < 2; mf++)
#pragma unroll
                for (int nf = 0; nf < 8; nf++) mma16816(acc[mf][nf], af[mf], bf[nf]);
        }
    }

#pragma unroll
    for (int mf = 0; mf < 2; mf++) {
#pragma unroll
        for (int rh = 0; rh < 2; rh++) {
            int gr = m0 + wm * 32 + mf * 16 + (lane >> 2) + rh * 8;
            float* op = out + (size_t)gr * DIM + n0;
#pragma unroll
            for (int nf = 0; nf < 8; nf++) {
                int lc = wn * 64 + nf * 8 + 2 * (lane & 3);
                *(float2*)(op + lc) = make_float2(acc[mf][nf][rh * 2 + 0] + sBias[lc],
                                                  acc[mf][nf][rh * 2 + 1] + sBias[lc + 1]);
            }
        }
    }
}

// ---------------- K/V projection GEMM (small M): round-1 proven 128x128 ----------------
// mode 0: fp32 raw out; mode 1: fp16 out
__global__ __launch_bounds__(256)
void k_gemm_s(const __half* __restrict__ A, const __half* __restrict__ W,
              const float* __restrict__ bias, int M,
              float* __restrict__ rawOut, __half* __restrict__ hOut, int mode) {
    __shared__ __align__(16) __half sA[2][128 * 40];
    __shared__ __align__(16) __half sB[2][128 * 40];

    const int tid = threadIdx.x, lane = tid & 31, wid = tid >> 5;
    const int wm = wid & 3, wn = wid >> 2;
    const int m0 = blockIdx.y * 128, n0 = blockIdx.x * 128;

    const int r0 = tid >> 2, r1 = r0 + 64;
    const int c0 = (tid & 3) * 8;
    const __half* Ab0 = A + (size_t)(m0 + r0) * DIM + c0;
    const __half* Ab1 = A + (size_t)(m0 + r1) * DIM + c0;
    const __half* Bb0 = W + (size_t)(n0 + r0) * DIM + c0;
    const __half* Bb1 = W + (size_t)(n0 + r1) * DIM + c0;
    const bool okA0 = (m0 + r0) < M, okA1 = (m0 + r1) < M;

    float acc[2][8][4];
#pragma unroll
    for (int i = 0; i < 2; i++)
#pragma unroll
        for (int j = 0; j < 8; j++)
#pragma unroll
            for (int k = 0; k < 4; k++) acc[i][j][k] = 0.f;

    const uint4 z4 = make_uint4(0, 0, 0, 0);
    uint4 ra0 = okA0 ? *(const uint4*)(Ab0) : z4;
    uint4 ra1 = okA1 ? *(const uint4*)(Ab1) : z4;
    uint4 rb0 = *(const uint4*)(Bb0);
    uint4 rb1 = *(const uint4*)(Bb1);

    const int NIT = DIM / 32;
    for (int it = 0; it < NIT; ++it) {
        __half* a_s = sA[it & 1];
        __half* b_s = sB[it & 1];
        *(uint4*)&a_s[r0 * 40 + c0] = ra0;
        *(uint4*)&a_s[r1 * 40 + c0] = ra1;
        *(uint4*)&b_s[r0 * 40 + c0] = rb0;
        *(uint4*)&b_s[r1 * 40 + c0] = rb1;
        __syncthreads();
        if (it + 1 < NIT) {
            int k = (it + 1) * 32;
            ra0 = okA0 ? *(const uint4*)(Ab0 + k) : z4;
            ra1 = okA1 ? *(const uint4*)(Ab1 + k) : z4;
            rb0 = *(const uint4*)(Bb0 + k);
            rb1 = *(const uint4*)(Bb1 + k);
        }
#pragma unroll
        for (int ks = 0; ks < 32; ks += 16) {
            uint32_t af[2][4];
#pragma unroll
            for (int mf = 0; mf < 2; mf++) {
                int mr = wm * 32 + mf * 16 + (lane & 7) + ((lane >> 3) & 1) * 8;
                int mc = ks + (lane >> 4) * 8;
                ldmx4(af[mf][0], af[mf][1], af[mf][2], af[mf][3], &a_s[mr * 40 + mc]);
            }
            uint32_t bf[8][2];
#pragma unroll
            for (int np = 0; np < 4; np++) {
                int nr = wn * 64 + np * 16 + (lane & 7) + ((lane >> 4) ? 8 : 0);
                int nc = ks + (((lane >> 3) & 1) ? 8 : 0);
                ldmx4(bf[2 * np][0], bf[2 * np][1], bf[2 * np + 1][0], bf[2 * np + 1][1],
                      &b_s[nr * 40 + nc]);
            }
#pragma unroll
            for (int mf = 0; mf < 2; mf++)
#pragma unroll
                for (int nf = 0; nf < 8; nf++) mma16816(acc[mf][nf], af[mf], bf[nf]);
        }
        __syncthreads();
    }

#pragma unroll
    for (int mf = 0; mf < 2; mf++) {
#pragma unroll
        for (int rh = 0; rh < 2; rh++) {
            int gr = m0 + wm * 32 + mf * 16 + (lane >> 2) + rh * 8;
            if (gr >= M) continue;
#pragma unroll
            for (int nf = 0; nf < 8; nf++) {
                int gc = n0 + wn * 64 + nf * 8 + 2 * (lane & 3);
                float v0 = acc[mf][nf][rh * 2 + 0] + bias[gc];
                float v1 = acc[mf][nf][rh * 2 + 1] + bias[gc + 1];
                if (mode == 0)
                    *(float2*)&rawOut[(size_t)gr * DIM + gc] = make_float2(v0, v1);
                else
                    *(__half2*)&hOut[(size_t)gr * DIM + gc] = __floats2half2_rn(v0, v1);
            }
        }
    }
}

// ---------------- fused attention (round-1, proven) ----------------
#define QK_STRIDE 136
#define PS_STRIDE 296
#define SMEM_QS   0
#define SMEM_KS   34816
#define SMEM_PS   (34816 + 78336)
#define SMEM_RS   (34816 + 78336 + 75776)
#define ATTN_SMEM (34816 + 78336 + 75776 + 512)

__global__ __launch_bounds__(256, 1)
void k_attn(float* __restrict__ out) {
    extern __shared__ __align__(16) char smem[];
    __half* Qs = (__half*)(smem + SMEM_QS);
    __half* Ks = (__half*)(smem + SMEM_KS);
    __half* Ps = (__half*)(smem + SMEM_PS);
    float* rowsum = (float*)(smem + SMEM_RS);

    const int tid = threadIdx.x, lane = tid & 31, wid = tid >> 5;
    const int wm = wid & 3, wn = wid >> 2;
    const int m0 = blockIdx.x * 128;
    const int h = blockIdx.y;
    const size_t hc = (size_t)h * HDIM;

    if (tid < 128) rowsum[tid] = 0.f;
#pragma unroll
    for (int i = 0; i < 8; i++) {
        int idx = tid + 256 * i;
        int r = idx >> 4, c = (idx & 15) * 8;
        *(uint4*)&Qs[r * QK_STRIDE + c] = *(const uint4*)&g_Qh[(size_t)(m0 + r) * DIM + hc + c];
    }
#pragma unroll
    for (int i = 0; i < 18; i++) {
        int idx = tid + 256 * i;
        int r = idx >> 4, c = (idx & 15) * 8;
        *(uint4*)&Ks[r * QK_STRIDE + c] = *(const uint4*)&g_Kh[(size_t)r * DIM + hc + c];
    }
    __syncthreads();

    const float SCALE = 0.088388347648318447f;
    for (int p = 0; p < 3; p++) {
        float acc[2][6][4];
#pragma unroll
        for (int i = 0; i < 2; i++)
#pragma unroll
            for (int j = 0; j < 6; j++)
#pragma unroll
                for (int k = 0; k < 4; k++) acc[i][j][k] = 0.f;

#pragma unroll
        for (int kk = 0; kk < 8; kk++) {
            int ks = kk * 16;
            uint32_t af[2][4];
#pragma unroll
            for (int mf = 0; mf < 2; mf++) {
                int mr = wm * 32 + mf * 16 + (lane & 7) + ((lane >> 3) & 1) * 8;
                int mc = ks + (lane >> 4) * 8;
                ldmx4(af[mf][0], af[mf][1], af[mf][2], af[mf][3], &Qs[mr * QK_STRIDE + mc]);
            }
            uint32_t bf[6][2];
#pragma unroll
            for (int np = 0; np < 3; np++) {
                int nr = p * 96 + wn * 48 + np * 16 + (lane & 7) + ((lane >> 4) ? 8 : 0);
                int nc = ks + (((lane >> 3) & 1) ? 8 : 0);
                ldmx4(bf[2 * np][0], bf[2 * np][1], bf[2 * np + 1][0], bf[2 * np + 1][1],
                      &Ks[nr * QK_STRIDE + nc]);
            }
#pragma unroll
            for (int mf = 0; mf < 2; mf++)
#pragma unroll
                for (int nf = 0; nf < 6; nf++) mma16816(acc[mf][nf], af[mf], bf[nf]);
        }
#pragma unroll
        for (int mf = 0; mf < 2; mf++) {
#pragma unroll
            for (int rh = 0; rh < 2; rh++) {
                int r = wm * 32 + mf * 16 + (lane >> 2) + rh * 8;
                float s = 0.f;
#pragma unroll
                for (int nf = 0; nf < 6; nf++) {
                    int col = p * 96 + wn * 48 + nf * 8 + 2 * (lane & 3);
                    float v0 = (col < KVLEN) ? __expf(acc[mf][nf][rh * 2 + 0] * SCALE) : 0.f;
                    float v1 = (col + 1 < KVLEN) ? __expf(acc[mf][nf][rh * 2 + 1] * SCALE) : 0.f;
                    *(__half2*)&Ps[r * PS_STRIDE + col] = __floats2half2_rn(v0, v1);
                    s += v0 + v1;
                }
                atomicAdd(&rowsum[r], s);
            }
        }
    }
    __syncthreads();
#pragma unroll
    for (int i = 0; i < 18; i++) {
        int idx = tid + 256 * i;
        int r = idx >> 4, c = (idx & 15) * 8;
        *(uint4*)&Ks[r * QK_STRIDE + c] = *(const uint4*)&g_Vh[(size_t)r * DIM + hc + c];
    }
    __syncthreads();

    float oc[2][8][4];
#pragma unroll
    for (int i = 0; i < 2; i++)
#pragma unroll
        for (int j = 0; j < 8; j++)
#pragma unroll
            for (int k = 0; k < 4; k++) oc[i][j][k] = 0.f;

    for (int kk = 0; kk < 18; kk++) {
        int ks = kk * 16;
        uint32_t af[2][4];
#pragma unroll
        for (int mf = 0; mf < 2; mf++) {
            int mr = wm * 32 + mf * 16 + (lane & 7) + ((lane >> 3) & 1) * 8;
            int mc = ks + (lane >> 4) * 8;
            ldmx4(af[mf][0], af[mf][1], af[mf][2], af[mf][3], &Ps[mr * PS_STRIDE + mc]);
        }
        uint32_t bf[8][2];
#pragma unroll
        for (int np = 0; np < 4; np++) {
            int vr = ks + (lane & 7) + ((lane >> 3) & 1) * 8;
            int vc = wn * 64 + np * 16 + (lane >> 4) * 8;
            ldmx4t(bf[2 * np][0], bf[2 * np][1], bf[2 * np + 1][0], bf[2 * np + 1][1],
                   &Ks[vr * QK_STRIDE + vc]);
        }
#pragma unroll
        for (int mf = 0; mf < 2; mf++)
#pragma unroll
            for (int nf = 0; nf < 8; nf++) mma16816(oc[mf][nf], af[mf], bf[nf]);
    }

#pragma unroll
    for (int mf = 0; mf < 2; mf++) {
#pragma unroll
        for (int rh = 0; rh < 2; rh++) {
            int r = wm * 32 + mf * 16 + (lane >> 2) + rh * 8;
            float inv = 1.0f / rowsum[r];
            size_t gro = (size_t)(m0 + r) * DIM + hc;
#pragma unroll
            for (int nf = 0; nf < 8; nf++) {
                int c = wn * 64 + nf * 8 + 2 * (lane & 3);
                *(float2*)&out[gro + c] =
                    make_float2(oc[mf][nf][rh * 2 + 0] * inv, oc[mf][nf][rh * 2 + 1] * inv);
            }
        }
    }
}

// ---------------- launcher ----------------
extern "C" void kernel_launch(void* const* d_in, const int* in_sizes, int n_in,
                              void* d_out, int out_size) {
    const float* hidden = (const float*)d_in[0];
    const float* enc = (const float*)d_in[1];
    const float* wq = (const float*)d_in[2];
    const float* bq = (const float*)d_in[3];
    const float* wk = (const float*)d_in[4];
    const float* bk = (const float*)d_in[5];
    const float* wv = (const float*)d_in[6];
    const float* bv = (const float*)d_in[7];
    const float* gq = (const float*)d_in[8];
    const float* gk = (const float*)d_in[9];
    float* out = (float*)d_out;

    void* p;
    cudaGetSymbolAddress(&p, g_Hh);    __half* Hh = (__half*)p;
    cudaGetSymbolAddress(&p, g_Eh);    __half* Eh = (__half*)p;
    cudaGetSymbolAddress(&p, g_Wqh);   __half* Wqh = (__half*)p;
    cudaGetSymbolAddress(&p, g_Wkh);   __half* Wkh = (__half*)p;
    cudaGetSymbolAddress(&p, g_Wvh);   __half* Wvh = (__half*)p;
    cudaGetSymbolAddress(&p, g_Qraw);  float* Qraw = (float*)p;
    cudaGetSymbolAddress(&p, g_Kraw);  float* Kraw = (float*)p;
    cudaGetSymbolAddress(&p, g_Qh);    __half* Qh = (__half*)p;
    cudaGetSymbolAddress(&p, g_Kh);    __half* Kh = (__half*)p;
    cudaGetSymbolAddress(&p, g_Vh);    __half* Vh = (__half*)p;

    // launches 0-4: conversions (Q-GEMM deps first so launch #5 is k_gemm_q for ncu)
    k_f2h<<<2048, 256>>>(hidden, Hh, SQ * DIM);
    k_f2h<<<1024, 256>>>(wq, Wqh, DIM * DIM);
    k_f2h<<<1024, 256>>>(wk, Wkh, DIM * DIM);
    k_f2h<<<1024, 256>>>(wv, Wvh, DIM * DIM);
    k_f2h<<<128, 256>>>(enc, Eh, KVLEN * DIM);

    // launch 5: the Q projection GEMM (ncu -s 5 captures this)
    cudaFuncSetAttribute(k_gemm_q, cudaFuncAttributeMaxDynamicSharedMemorySize, G_SMEM);
    k_gemm_q<<<dim3(20, 128), 512, G_SMEM>>>(Hh, Wqh, bq, Qraw);

    // K/V projections (small-M kernel)
    k_gemm_s<<<dim3(40, 3), 256>>>(Eh, Wkh, bk, KVLEN, Kraw, ((__half*)0), 0);
    k_gemm_s<<<dim3(40, 3), 256>>>(Eh, Wvh, bv, KVLEN, ((float*)0), Vh, 1);

    // rmsnorm (fused ssq) -> fp16
    k_norm<<<SQ, 256>>>(Qraw, gq, Qh, SQ);
    k_norm<<<KVLEN, 256>>>(Kraw, gk, Kh, KVLEN);

    // attention
    cudaFuncSetAttribute(k_attn, cudaFuncAttributeMaxDynamicSharedMemorySize, ATTN_SMEM);
    k_attn<<<dim3(128, NHEADS), 256, ATTN_SMEM>>>(out);
}

// round 5
// speedup vs baseline: 1.0828x; 1.0551x over previous
#include <cuda_runtime.h>
#include <cuda_fp16.h>
#include <stdint.h>

#define DIM    5120
#define SQ     16384
#define KVLEN  257
#define KVP    288
#define NHEADS 40
#define HDIM   128
#define INV_DIM (1.0f / 5120.0f)
#define RMS_EPS 1e-6f

// ---------------- scratch (device globals; no allocs allowed) ----------------
__device__ __half g_Hh  [(size_t)SQ * DIM];
__device__ __half g_Eh  [(size_t)KVLEN * DIM];
__device__ __half g_Wqh [(size_t)DIM * DIM];
__device__ __half g_Wkh [(size_t)DIM * DIM];
__device__ __half g_Wvh [(size_t)DIM * DIM];
__device__ __half g_Qh  [(size_t)SQ * DIM];    // raw q (pre-norm), fp16
__device__ __half g_Kh  [(size_t)KVP * DIM];   // raw k; rows >= 257 stay zero
__device__ __half g_Vh  [(size_t)KVP * DIM];   // v; rows >= 257 stay zero
__device__ float  g_ssq_q[SQ];
__device__ float  g_ssq_k[KVLEN];

// ---------------- helpers ----------------
__device__ __forceinline__ uint32_t smem_u32(const void* p) {
    return (uint32_t)__cvta_generic_to_shared(p);
}

__device__ __forceinline__ void ldmx4(uint32_t& r0, uint32_t& r1, uint32_t& r2, uint32_t& r3,
                                      const __half* p) {
    asm volatile("ldmatrix.sync.aligned.m8n8.x4.shared.b16 {%0,%1,%2,%3}, [%4];"
                 : "=r"(r0), "=r"(r1), "=r"(r2), "=r"(r3)
                 : "r"(smem_u32(p)));
}

__device__ __forceinline__ void ldmx4t(uint32_t& r0, uint32_t& r1, uint32_t& r2, uint32_t& r3,
                                       const __half* p) {
    asm volatile("ldmatrix.sync.aligned.m8n8.x4.trans.shared.b16 {%0,%1,%2,%3}, [%4];"
                 : "=r"(r0), "=r"(r1), "=r"(r2), "=r"(r3)
                 : "r"(smem_u32(p)));
}

__device__ __forceinline__ void mma16816(float* c, const uint32_t* a, const uint32_t* b) {
    asm volatile(
        "mma.sync.aligned.m16n8k16.row.col.f32.f16.f16.f32 "
        "{%0,%1,%2,%3},{%4,%5,%6,%7},{%8,%9},{%0,%1,%2,%3};"
        : "+f"(c[0]), "+f"(c[1]), "+f"(c[2]), "+f"(c[3])
        : "r"(a[0]), "r"(a[1]), "r"(a[2]), "r"(a[3]), "r"(b[0]), "r"(b[1]));
}

// ---------------- prep kernels ----------------
// launch 0: convert H + Wq to fp16, zero ssq arrays (everything gemm_q needs)
__global__ void k_prep_hwq(const float* __restrict__ H, const float* __restrict__ Wq) {
    const size_t PH = (size_t)SQ * DIM / 2;
    const size_t PW = (size_t)DIM * DIM / 2;
    size_t i0 = (size_t)blockIdx.x * blockDim.x + threadIdx.x;
    size_t st = (size_t)gridDim.x * blockDim.x;
    if (i0 < SQ) g_ssq_q[i0] = 0.f;
    if (i0 < KVLEN) g_ssq_k[i0] = 0.f;
    for (size_t i = i0; i < PH + PW; i += st) {
        if (i < PH) {
            float2 v = ((const float2*)H)[i];
            ((__half2*)g_Hh)[i] = __floats2half2_rn(v.x, v.y);
        } else {
            float2 v = ((const float2*)Wq)[i - PH];
            ((__half2*)g_Wqh)[i - PH] = __floats2half2_rn(v.x, v.y);
        }
    }
}

// launch 2: convert Wk, Wv, enc
__global__ void k_prep_rest(const float* __restrict__ Wk, const float* __restrict__ Wv,
                            const float* __restrict__ E) {
    const size_t PW = (size_t)DIM * DIM / 2;
    const size_t PE = (size_t)KVLEN * DIM / 2;
    size_t i0 = (size_t)blockIdx.x * blockDim.x + threadIdx.x;
    size_t st = (size_t)gridDim.x * blockDim.x;
    for (size_t i = i0; i < 2 * PW + PE; i += st) {
        if (i < PW) {
            float2 v = ((const float2*)Wk)[i];
            ((__half2*)g_Wkh)[i] = __floats2half2_rn(v.x, v.y);
        } else if (i < 2 * PW) {
            float2 v = ((const float2*)Wv)[i - PW];
            ((__half2*)g_Wvh)[i - PW] = __floats2half2_rn(v.x, v.y);
        } else {
            float2 v = ((const float2*)E)[i - 2 * PW];
            ((__half2*)g_Eh)[i - 2 * PW] = __floats2half2_rn(v.x, v.y);
        }
    }
}

// ---------------- projection GEMM (round-1 proven core) ----------------
// out[m,n] = fp16(sum_k A[m,k]*W[n,k] + bias[n]); if ssq != null, atomicAdd row sum-sq.
// BM=BN=128, BK=32; 8 warps (4m x 2n); register-staged double buffer.
__global__ __launch_bounds__(256)
void k_proj(const __half* __restrict__ A, const __half* __restrict__ W,
            const float* __restrict__ bias, int M,
            __half* __restrict__ out, float* __restrict__ ssq) {
    __shared__ __align__(16) __half sA[2][128 * 40];
    __shared__ __align__(16) __half sB[2][128 * 40];

    const int tid = threadIdx.x, lane = tid & 31, wid = tid >> 5;
    const int wm = wid & 3, wn = wid >> 2;
    const int m0 = blockIdx.y * 128, n0 = blockIdx.x * 128;

    const int r0 = tid >> 2, r1 = r0 + 64;
    const int c0 = (tid & 3) * 8;
    const __half* Ab0 = A + (size_t)(m0 + r0) * DIM + c0;
    const __half* Ab1 = A + (size_t)(m0 + r1) * DIM + c0;
    const __half* Bb0 = W + (size_t)(n0 + r0) * DIM + c0;
    const __half* Bb1 = W + (size_t)(n0 + r1) * DIM + c0;
    const bool okA0 = (m0 + r0) < M, okA1 = (m0 + r1) < M;

    float acc[2][8][4];
#pragma unroll
    for (int i = 0; i < 2; i++)
#pragma unroll
        for (int j = 0; j < 8; j++)
#pragma unroll
            for (int k = 0; k < 4; k++) acc[i][j][k] = 0.f;

    const uint4 z4 = make_uint4(0, 0, 0, 0);
    uint4 ra0 = okA0 ? *(const uint4*)(Ab0) : z4;
    uint4 ra1 = okA1 ? *(const uint4*)(Ab1) : z4;
    uint4 rb0 = *(const uint4*)(Bb0);
    uint4 rb1 = *(const uint4*)(Bb1);

    const int NIT = DIM / 32;  // 160
    for (int it = 0; it < NIT; ++it) {
        __half* a_s = sA[it & 1];
        __half* b_s = sB[it & 1];
        *(uint4*)&a_s[r0 * 40 + c0] = ra0;
        *(uint4*)&a_s[r1 * 40 + c0] = ra1;
        *(uint4*)&b_s[r0 * 40 + c0] = rb0;
        *(uint4*)&b_s[r1 * 40 + c0] = rb1;
        __syncthreads();
        if (it + 1 < NIT) {
            int k = (it + 1) * 32;
            ra0 = okA0 ? *(const uint4*)(Ab0 + k) : z4;
            ra1 = okA1 ? *(const uint4*)(Ab1 + k) : z4;
            rb0 = *(const uint4*)(Bb0 + k);
            rb1 = *(const uint4*)(Bb1 + k);
        }
#pragma unroll
        for (int ks = 0; ks < 32; ks += 16) {
            uint32_t af[2][4];
#pragma unroll
            for (int mf = 0; mf < 2; mf++) {
                int mr = wm * 32 + mf * 16 + (lane & 7) + ((lane >> 3) & 1) * 8;
                int mc = ks + (lane >> 4) * 8;
                ldmx4(af[mf][0], af[mf][1], af[mf][2], af[mf][3], &a_s[mr * 40 + mc]);
            }
            uint32_t bf[8][2];
#pragma unroll
            for (int np = 0; np < 4; np++) {
                int nr = wn * 64 + np * 16 + (lane & 7) + ((lane >> 4) ? 8 : 0);
                int nc = ks + (((lane >> 3) & 1) ? 8 : 0);
                ldmx4(bf[2 * np][0], bf[2 * np][1], bf[2 * np + 1][0], bf[2 * np + 1][1],
                      &b_s[nr * 40 + nc]);
            }
#pragma unroll
            for (int mf = 0; mf < 2; mf++)
#pragma unroll
                for (int nf = 0; nf < 8; nf++) mma16816(acc[mf][nf], af[mf], bf[nf]);
        }
        __syncthreads();
    }

    // epilogue: fp16 store (+ optional row sum-of-squares from fp32 accumulators)
#pragma unroll
    for (int mf = 0; mf < 2; mf++) {
#pragma unroll
        for (int rh = 0; rh < 2; rh++) {
            int gr = m0 + wm * 32 + mf * 16 + (lane >> 2) + rh * 8;
            if (gr >= M) continue;
            float s = 0.f;
#pragma unroll
            for (int nf = 0; nf < 8; nf++) {
                int gc = n0 + wn * 64 + nf * 8 + 2 * (lane & 3);
                float v0 = acc[mf][nf][rh * 2 + 0] + bias[gc];
                float v1 = acc[mf][nf][rh * 2 + 1] + bias[gc + 1];
                s += v0 * v0 + v1 * v1;
                *(__half2*)&out[(size_t)gr * DIM + gc] = __floats2half2_rn(v0, v1);
            }
            if (ssq) atomicAdd(&ssq[gr], s);
        }
    }
}

// ---------------- fused attention (+ folded rmsnorm of Q and K) ----------------
#define QK_STRIDE 136
#define PS_STRIDE 296
#define SMEM_QS   0
#define SMEM_KS   34816
#define SMEM_PS   (34816 + 78336)
#define SMEM_RS   (34816 + 78336 + 75776)
#define ATTN_SMEM (34816 + 78336 + 75776 + 512)

__global__ __launch_bounds__(256, 1)
void k_attn(const float* __restrict__ gq, const float* __restrict__ gk,
            float* __restrict__ out) {
    extern __shared__ __align__(16) char smem[];
    __half* Qs = (__half*)(smem + SMEM_QS);
    __half* Ks = (__half*)(smem + SMEM_KS);  // reused for V in phase 2
    __half* Ps = (__half*)(smem + SMEM_PS);
    float* rowsum = (float*)(smem + SMEM_RS);

    const int tid = threadIdx.x, lane = tid & 31, wid = tid >> 5;
    const int wm = wid & 3, wn = wid >> 2;
    const int m0 = blockIdx.x * 128;
    const int h = blockIdx.y;
    const size_t hc = (size_t)h * HDIM;

    if (tid < 128) rowsum[tid] = 0.f;

    // Q tile 128x128: raw fp16 * rsqrt(ssq/D+eps) * g
#pragma unroll
    for (int i = 0; i < 8; i++) {
        int idx = tid + 256 * i;
        int r = idx >> 4, c = (idx & 15) * 8;
        float sc = rsqrtf(g_ssq_q[m0 + r] * INV_DIM + RMS_EPS);
        uint4 v = *(const uint4*)&g_Qh[(size_t)(m0 + r) * DIM + hc + c];
        __half2* hv = (__half2*)&v;
        const float2* gp = (const float2*)(gq + hc + c);
#pragma unroll
        for (int j = 0; j < 4; j++) {
            float2 f = __half22float2(hv[j]);
            float2 g2 = gp[j];
            hv[j] = __floats2half2_rn(f.x * sc * g2.x, f.y * sc * g2.y);
        }
        *(uint4*)&Qs[r * QK_STRIDE + c] = v;
    }
    // K tile 288x128: raw fp16 (rows>=257 are zero) * scale * g
#pragma unroll
    for (int i = 0; i < 18; i++) {
        int idx = tid + 256 * i;
        int r = idx >> 4, c = (idx & 15) * 8;
        int rr = r < KVLEN ? r : KVLEN - 1;
        float sc = rsqrtf(g_ssq_k[rr] * INV_DIM + RMS_EPS);
        uint4 v = *(const uint4*)&g_Kh[(size_t)r * DIM + hc + c];
        __half2* hv = (__half2*)&v;
        const float2* gp = (const float2*)(gk + hc + c);
#pragma unroll
        for (int j = 0; j < 4; j++) {
            float2 f = __half22float2(hv[j]);
            float2 g2 = gp[j];
            hv[j] = __floats2half2_rn(f.x * sc * g2.x, f.y * sc * g2.y);
        }
        *(uint4*)&Ks[r * QK_STRIDE + c] = v;
    }
    __syncthreads();

    const float SCALE = 0.088388347648318447f;  // 1/sqrt(128)
    for (int p = 0; p < 3; p++) {
        float acc[2][6][4];
#pragma unroll
        for (int i = 0; i < 2; i++)
#pragma unroll
            for (int j = 0; j < 6; j++)
#pragma unroll
                for (int k = 0; k < 4; k++) acc[i][j][k] = 0.f;

#pragma unroll
        for (int kk = 0; kk < 8; kk++) {
            int ks = kk * 16;
            uint32_t af[2][4];
#pragma unroll
            for (int mf = 0; mf < 2; mf++) {
                int mr = wm * 32 + mf * 16 + (lane & 7) + ((lane >> 3) & 1) * 8;
                int mc = ks + (lane >> 4) * 8;
                ldmx4(af[mf][0], af[mf][1], af[mf][2], af[mf][3], &Qs[mr * QK_STRIDE + mc]);
            }
            uint32_t bf[6][2];
#pragma unroll
            for (int np = 0; np < 3; np++) {
                int nr = p * 96 + wn * 48 + np * 16 + (lane & 7) + ((lane >> 4) ? 8 : 0);
                int nc = ks + (((lane >> 3) & 1) ? 8 : 0);
                ldmx4(bf[2 * np][0], bf[2 * np][1], bf[2 * np + 1][0], bf[2 * np + 1][1],
                      &Ks[nr * QK_STRIDE + nc]);
            }
#pragma unroll
            for (int mf = 0; mf < 2; mf++)
#pragma unroll
                for (int nf = 0; nf < 6; nf++) mma16816(acc[mf][nf], af[mf], bf[nf]);
        }
#pragma unroll
        for (int mf = 0; mf < 2; mf++) {
#pragma unroll
            for (int rh = 0; rh < 2; rh++) {
                int r = wm * 32 + mf * 16 + (lane >> 2) + rh * 8;
                float s = 0.f;
#pragma unroll
                for (int nf = 0; nf < 6; nf++) {
                    int col = p * 96 + wn * 48 + nf * 8 + 2 * (lane & 3);
                    float v0 = (col < KVLEN) ? __expf(acc[mf][nf][rh * 2 + 0] * SCALE) : 0.f;
                    float v1 = (col + 1 < KVLEN) ? __expf(acc[mf][nf][rh * 2 + 1] * SCALE) : 0.f;
                    *(__half2*)&Ps[r * PS_STRIDE + col] = __floats2half2_rn(v0, v1);
                    s += v0 + v1;
                }
                atomicAdd(&rowsum[r], s);
            }
        }
    }
    __syncthreads();
    // V replaces K (no normalization for V)
#pragma unroll
    for (int i = 0; i < 18; i++) {
        int idx = tid + 256 * i;
        int r = idx >> 4, c = (idx & 15) * 8;
        *(uint4*)&Ks[r * QK_STRIDE + c] = *(const uint4*)&g_Vh[(size_t)r * DIM + hc + c];
    }
    __syncthreads();

    float oc[2][8][4];
#pragma unroll
    for (int i = 0; i < 2; i++)
#pragma unroll
        for (int j = 0; j < 8; j++)
#pragma unroll
            for (int k = 0; k < 4; k++) oc[i][j][k] = 0.f;

    // 272 cols cover all nonzero P (257) rounded up to 16
    for (int kk = 0; kk < 17; kk++) {
        int ks = kk * 16;
        uint32_t af[2][4];
#pragma unroll
        for (int mf = 0; mf < 2; mf++) {
            int mr = wm * 32 + mf * 16 + (lane & 7) + ((lane >> 3) & 1) * 8;
            int mc = ks + (lane >> 4) * 8;
            ldmx4(af[mf][0], af[mf][1], af[mf][2], af[mf][3], &Ps[mr * PS_STRIDE + mc]);
        }
        uint32_t bf[8][2];
#pragma unroll
        for (int np = 0; np < 4; np++) {
            int vr = ks + (lane & 7) + ((lane >> 3) & 1) * 8;
            int vc = wn * 64 + np * 16 + (lane >> 4) * 8;
            ldmx4t(bf[2 * np][0], bf[2 * np][1], bf[2 * np + 1][0], bf[2 * np + 1][1],
                   &Ks[vr * QK_STRIDE + vc]);
        }
#pragma unroll
        for (int mf = 0; mf < 2; mf++)
#pragma unroll
            for (int nf = 0; nf < 8; nf++) mma16816(oc[mf][nf], af[mf], bf[nf]);
    }

#pragma unroll
    for (int mf = 0; mf < 2; mf++) {
#pragma unroll
        for (int rh = 0; rh < 2; rh++) {
            int r = wm * 32 + mf * 16 + (lane >> 2) + rh * 8;
            float inv = 1.0f / rowsum[r];
            size_t gro = (size_t)(m0 + r) * DIM + hc;
#pragma unroll
            for (int nf = 0; nf < 8; nf++) {
                int c = wn * 64 + nf * 8 + 2 * (lane & 3);
                *(float2*)&out[gro + c] =
                    make_float2(oc[mf][nf][rh * 2 + 0] * inv, oc[mf][nf][rh * 2 + 1] * inv);
            }
        }
    }
}

// ---------------- launcher ----------------
extern "C" void kernel_launch(void* const* d_in, const int* in_sizes, int n_in,
                              void* d_out, int out_size) {
    const float* hidden = (const float*)d_in[0];
    const float* enc = (const float*)d_in[1];
    const float* wq = (const float*)d_in[2];
    const float* bq = (const float*)d_in[3];
    const float* wk = (const float*)d_in[4];
    const float* bk = (const float*)d_in[5];
    const float* wv = (const float*)d_in[6];
    const float* bv = (const float*)d_in[7];
    const float* gq = (const float*)d_in[8];
    const float* gk = (const float*)d_in[9];
    float* out = (float*)d_out;

    void* p;
    cudaGetSymbolAddress(&p, g_Hh);    __half* Hh = (__half*)p;
    cudaGetSymbolAddress(&p, g_Eh);    __half* Eh = (__half*)p;
    cudaGetSymbolAddress(&p, g_Wqh);   __half* Wqh = (__half*)p;
    cudaGetSymbolAddress(&p, g_Wkh);   __half* Wkh = (__half*)p;
    cudaGetSymbolAddress(&p, g_Wvh);   __half* Wvh = (__half*)p;
    cudaGetSymbolAddress(&p, g_Qh);    __half* Qh = (__half*)p;
    cudaGetSymbolAddress(&p, g_Kh);    __half* Kh = (__half*)p;
    cudaGetSymbolAddress(&p, g_Vh);    __half* Vh = (__half*)p;
    cudaGetSymbolAddress(&p, g_ssq_q); float* ssq_q = (float*)p;
    cudaGetSymbolAddress(&p, g_ssq_k); float* ssq_k = (float*)p;

    // launch 0: everything gemm_q needs (H + Wq fp16, ssq zeroed)
    k_prep_hwq<<<4096, 256>>>(hidden, wq);

    // launch 1: Q projection GEMM (ncu -s 5 lands here: 4 harness launches + prep)
    k_proj<<<dim3(40, 128), 256>>>(Hh, Wqh, bq, SQ, Qh, ssq_q);

    // launch 2: remaining conversions
    k_prep_rest<<<2048, 256>>>(wk, wv, enc);

    // launches 3-4: K/V projections
    k_proj<<<dim3(40, 3), 256>>>(Eh, Wkh, bk, KVLEN, Kh, ssq_k);
    k_proj<<<dim3(40, 3), 256>>>(Eh, Wvh, bv, KVLEN, Vh, (float*)0);

    // launch 5: attention with folded rmsnorm
    cudaFuncSetAttribute(k_attn, cudaFuncAttributeMaxDynamicSharedMemorySize, ATTN_SMEM);
    k_attn<<<dim3(128, NHEADS), 256, ATTN_SMEM>>>(gq, gk, out);
}

// round 6
// speedup vs baseline: 1.0940x; 1.0103x over previous
#include <cuda_runtime.h>
#include <cuda_fp16.h>
#include <stdint.h>

#define DIM    5120
#define SQ     16384
#define KVLEN  257
#define KVP    288
#define NHEADS 40
#define HDIM   128
#define INV_DIM (1.0f / 5120.0f)
#define RMS_EPS 1e-6f

// ---------------- scratch (device globals; no allocs allowed) ----------------
__device__ __half g_Hh  [(size_t)SQ * DIM];
__device__ __half g_Eh  [(size_t)KVLEN * DIM];
__device__ __half g_Wqh [(size_t)DIM * DIM];
__device__ __half g_Wkh [(size_t)DIM * DIM];
__device__ __half g_Wvh [(size_t)DIM * DIM];
__device__ __half g_Qh  [(size_t)SQ * DIM];    // raw q (pre-norm), fp16
__device__ __half g_Kh  [(size_t)KVP * DIM];   // raw k; rows >= 257 stay zero
__device__ __half g_Vh  [(size_t)KVP * DIM];   // v; rows >= 257 stay zero
__device__ float  g_ssq_q[SQ];
__device__ float  g_ssq_k[KVLEN];

// ---------------- helpers ----------------
__device__ __forceinline__ uint32_t smem_u32(const void* p) {
    return (uint32_t)__cvta_generic_to_shared(p);
}

__device__ __forceinline__ void ldmx4(uint32_t& r0, uint32_t& r1, uint32_t& r2, uint32_t& r3,
                                      const __half* p) {
    asm volatile("ldmatrix.sync.aligned.m8n8.x4.shared.b16 {%0,%1,%2,%3}, [%4];"
                 : "=r"(r0), "=r"(r1), "=r"(r2), "=r"(r3)
                 : "r"(smem_u32(p)));
}

__device__ __forceinline__ void ldmx4t(uint32_t& r0, uint32_t& r1, uint32_t& r2, uint32_t& r3,
                                       const __half* p) {
    asm volatile("ldmatrix.sync.aligned.m8n8.x4.trans.shared.b16 {%0,%1,%2,%3}, [%4];"
                 : "=r"(r0), "=r"(r1), "=r"(r2), "=r"(r3)
                 : "r"(smem_u32(p)));
}

__device__ __forceinline__ void mma16816(float* c, const uint32_t* a, const uint32_t* b) {
    asm volatile(
        "mma.sync.aligned.m16n8k16.row.col.f32.f16.f16.f32 "
        "{%0,%1,%2,%3},{%4,%5,%6,%7},{%8,%9},{%0,%1,%2,%3};"
        : "+f"(c[0]), "+f"(c[1]), "+f"(c[2]), "+f"(c[3])
        : "r"(a[0]), "r"(a[1]), "r"(a[2]), "r"(a[3]), "r"(b[0]), "r"(b[1]));
}

// ---------------- prep kernels ----------------
// launch 0: convert H + Wq to fp16, zero ssq arrays (everything gemm_q needs)
__global__ void k_prep_hwq(const float* __restrict__ H, const float* __restrict__ Wq) {
    const size_t PH = (size_t)SQ * DIM / 2;
    const size_t PW = (size_t)DIM * DIM / 2;
    size_t i0 = (size_t)blockIdx.x * blockDim.x + threadIdx.x;
    size_t st = (size_t)gridDim.x * blockDim.x;
    if (i0 < SQ) g_ssq_q[i0] = 0.f;
    if (i0 < KVLEN) g_ssq_k[i0] = 0.f;
    for (size_t i = i0; i < PH + PW; i += st) {
        if (i < PH) {
            float2 v = ((const float2*)H)[i];
            ((__half2*)g_Hh)[i] = __floats2half2_rn(v.x, v.y);
        } else {
            float2 v = ((const float2*)Wq)[i - PH];
            ((__half2*)g_Wqh)[i - PH] = __floats2half2_rn(v.x, v.y);
        }
    }
}

// launch 1: convert Wk, Wv, enc
__global__ void k_prep_rest(const float* __restrict__ Wk, const float* __restrict__ Wv,
                            const float* __restrict__ E) {
    const size_t PW = (size_t)DIM * DIM / 2;
    const size_t PE = (size_t)KVLEN * DIM / 2;
    size_t i0 = (size_t)blockIdx.x * blockDim.x + threadIdx.x;
    size_t st = (size_t)gridDim.x * blockDim.x;
    for (size_t i = i0; i < 2 * PW + PE; i += st) {
        if (i < PW) {
            float2 v = ((const float2*)Wk)[i];
            ((__half2*)g_Wkh)[i] = __floats2half2_rn(v.x, v.y);
        } else if (i < 2 * PW) {
            float2 v = ((const float2*)Wv)[i - PW];
            ((__half2*)g_Wvh)[i - PW] = __floats2half2_rn(v.x, v.y);
        } else {
            float2 v = ((const float2*)E)[i - 2 * PW];
            ((__half2*)g_Eh)[i - 2 * PW] = __floats2half2_rn(v.x, v.y);
        }
    }
}

// ---------------- projection GEMM core (shared by Q and KV kernels) ----------------
// out[m,n] = fp16(sum_k A[m,k]*W[n,k] + bias[n]); if ssq != null, atomicAdd row sum-sq.
// BM=BN=128, BK=32; 8 warps (4m x 2n); register-staged double buffer.
__device__ __forceinline__
void proj_body(const __half* __restrict__ A, const __half* __restrict__ W,
               const float* __restrict__ bias, int M,
               __half* __restrict__ out, float* __restrict__ ssq,
               int m0, int n0) {
    __shared__ __align__(16) __half sA[2][128 * 40];
    __shared__ __align__(16) __half sB[2][128 * 40];

    const int tid = threadIdx.x, lane = tid & 31, wid = tid >> 5;
    const int wm = wid & 3, wn = wid >> 2;

    const int r0 = tid >> 2, r1 = r0 + 64;
    const int c0 = (tid & 3) * 8;
    const __half* Ab0 = A + (size_t)(m0 + r0) * DIM + c0;
    const __half* Ab1 = A + (size_t)(m0 + r1) * DIM + c0;
    const __half* Bb0 = W + (size_t)(n0 + r0) * DIM + c0;
    const __half* Bb1 = W + (size_t)(n0 + r1) * DIM + c0;
    const bool okA0 = (m0 + r0) < M, okA1 = (m0 + r1) < M;

    float acc[2][8][4];
#pragma unroll
    for (int i = 0; i < 2; i++)
#pragma unroll
        for (int j = 0; j < 8; j++)
#pragma unroll
            for (int k = 0; k < 4; k++) acc[i][j][k] = 0.f;

    const uint4 z4 = make_uint4(0, 0, 0, 0);
    uint4 ra0 = okA0 ? *(const uint4*)(Ab0) : z4;
    uint4 ra1 = okA1 ? *(const uint4*)(Ab1) : z4;
    uint4 rb0 = *(const uint4*)(Bb0);
    uint4 rb1 = *(const uint4*)(Bb1);

    const int NIT = DIM / 32;  // 160
    for (int it = 0; it < NIT; ++it) {
        __half* a_s = sA[it & 1];
        __half* b_s = sB[it & 1];
        *(uint4*)&a_s[r0 * 40 + c0] = ra0;
        *(uint4*)&a_s[r1 * 40 + c0] = ra1;
        *(uint4*)&b_s[r0 * 40 + c0] = rb0;
        *(uint4*)&b_s[r1 * 40 + c0] = rb1;
        __syncthreads();
        if (it + 1 < NIT) {
            int k = (it + 1) * 32;
            ra0 = okA0 ? *(const uint4*)(Ab0 + k) : z4;
            ra1 = okA1 ? *(const uint4*)(Ab1 + k) : z4;
            rb0 = *(const uint4*)(Bb0 + k);
            rb1 = *(const uint4*)(Bb1 + k);
        }
#pragma unroll
        for (int ks = 0; ks < 32; ks += 16) {
            uint32_t af[2][4];
#pragma unroll
            for (int mf = 0; mf < 2; mf++) {
                int mr = wm * 32 + mf * 16 + (lane & 7) + ((lane >> 3) & 1) * 8;
                int mc = ks + (lane >> 4) * 8;
                ldmx4(af[mf][0], af[mf][1], af[mf][2], af[mf][3], &a_s[mr * 40 + mc]);
            }
            uint32_t bf[8][2];
#pragma unroll
            for (int np = 0; np < 4; np++) {
                int nr = wn * 64 + np * 16 + (lane & 7) + ((lane >> 4) ? 8 : 0);
                int nc = ks + (((lane >> 3) & 1) ? 8 : 0);
                ldmx4(bf[2 * np][0], bf[2 * np][1], bf[2 * np + 1][0], bf[2 * np + 1][1],
                      &b_s[nr * 40 + nc]);
            }
#pragma unroll
            for (int mf = 0; mf < 2; mf++)
#pragma unroll
                for (int nf = 0; nf < 8; nf++) mma16816(acc[mf][nf], af[mf], bf[nf]);
        }
        __syncthreads();
    }

    // epilogue: fp16 store (+ optional row sum-of-squares from fp32 accumulators)
#pragma unroll
    for (int mf = 0; mf < 2; mf++) {
#pragma unroll
        for (int rh = 0; rh < 2; rh++) {
            int gr = m0 + wm * 32 + mf * 16 + (lane >> 2) + rh * 8;
            if (gr >= M) continue;
            float s = 0.f;
#pragma unroll
            for (int nf = 0; nf < 8; nf++) {
                int gc = n0 + wn * 64 + nf * 8 + 2 * (lane & 3);
                float v0 = acc[mf][nf][rh * 2 + 0] + bias[gc];
                float v1 = acc[mf][nf][rh * 2 + 1] + bias[gc + 1];
                s += v0 * v0 + v1 * v1;
                *(__half2*)&out[(size_t)gr * DIM + gc] = __floats2half2_rn(v0, v1);
            }
            if (ssq) atomicAdd(&ssq[gr], s);
        }
    }
}

// Q projection: force 2 CTAs/SM (register cap)
__global__ __launch_bounds__(256, 2)
void k_proj_q(const __half* __restrict__ A, const __half* __restrict__ W,
              const float* __restrict__ bias, __half* __restrict__ out,
              float* __restrict__ ssq) {
    proj_body(A, W, bias, SQ, out, ssq, blockIdx.y * 128, blockIdx.x * 128);
}

// K and V projections merged: z=0 -> K (with ssq), z=1 -> V
__global__ __launch_bounds__(256, 2)
void k_proj_kv(const __half* __restrict__ E,
               const __half* __restrict__ Wk, const __half* __restrict__ Wv,
               const float* __restrict__ bk, const float* __restrict__ bv,
               __half* __restrict__ Kh, __half* __restrict__ Vh,
               float* __restrict__ ssq_k) {
    if (blockIdx.z == 0)
        proj_body(E, Wk, bk, KVLEN, Kh, ssq_k, blockIdx.y * 128, blockIdx.x * 128);
    else
        proj_body(E, Wv, bv, KVLEN, Vh, (float*)0, blockIdx.y * 128, blockIdx.x * 128);
}

// ---------------- fused attention (+ folded rmsnorm of Q and K) ----------------
#define QK_STRIDE 136
#define PS_STRIDE 296
#define SMEM_QS   0
#define SMEM_KS   34816
#define SMEM_PS   (34816 + 78336)
#define SMEM_RS   (34816 + 78336 + 75776)
#define ATTN_SMEM (34816 + 78336 + 75776 + 512)

__global__ __launch_bounds__(256, 1)
void k_attn(const float* __restrict__ gq, const float* __restrict__ gk,
            float* __restrict__ out) {
    extern __shared__ __align__(16) char smem[];
    __half* Qs = (__half*)(smem + SMEM_QS);
    __half* Ks = (__half*)(smem + SMEM_KS);  // reused for V in phase 2
    __half* Ps = (__half*)(smem + SMEM_PS);
    float* rowsum = (float*)(smem + SMEM_RS);

    const int tid = threadIdx.x, lane = tid & 31, wid = tid >> 5;
    const int wm = wid & 3, wn = wid >> 2;
    const int m0 = blockIdx.x * 128;
    const int h = blockIdx.y;
    const size_t hc = (size_t)h * HDIM;

    if (tid < 128) rowsum[tid] = 0.f;

    // Q tile 128x128: raw fp16 * rsqrt(ssq/D+eps) * g
#pragma unroll
    for (int i = 0; i < 8; i++) {
        int idx = tid + 256 * i;
        int r = idx >> 4, c = (idx & 15) * 8;
        float sc = rsqrtf(g_ssq_q[m0 + r] * INV_DIM + RMS_EPS);
        uint4 v = *(const uint4*)&g_Qh[(size_t)(m0 + r) * DIM + hc + c];
        __half2* hv = (__half2*)&v;
        const float2* gp = (const float2*)(gq + hc + c);
#pragma unroll
        for (int j = 0; j < 4; j++) {
            float2 f = __half22float2(hv[j]);
            float2 g2 = gp[j];
            hv[j] = __floats2half2_rn(f.x * sc * g2.x, f.y * sc * g2.y);
        }
        *(uint4*)&Qs[r * QK_STRIDE + c] = v;
    }
    // K tile 288x128: raw fp16 (rows>=257 are zero) * scale * g
#pragma unroll
    for (int i = 0; i < 18; i++) {
        int idx = tid + 256 * i;
        int r = idx >> 4, c = (idx & 15) * 8;
        int rr = r < KVLEN ? r : KVLEN - 1;
        float sc = rsqrtf(g_ssq_k[rr] * INV_DIM + RMS_EPS);
        uint4 v = *(const uint4*)&g_Kh[(size_t)r * DIM + hc + c];
        __half2* hv = (__half2*)&v;
        const float2* gp = (const float2*)(gk + hc + c);
#pragma unroll
        for (int j = 0; j < 4; j++) {
            float2 f = __half22float2(hv[j]);
            float2 g2 = gp[j];
            hv[j] = __floats2half2_rn(f.x * sc * g2.x, f.y * sc * g2.y);
        }
        *(uint4*)&Ks[r * QK_STRIDE + c] = v;
    }
    __syncthreads();

    const float SCALE = 0.088388347648318447f;  // 1/sqrt(128)
    for (int p = 0; p < 3; p++) {
        float acc[2][6][4];
#pragma unroll
        for (int i = 0; i < 2; i++)
#pragma unroll
            for (int j = 0; j < 6; j++)
#pragma unroll
                for (int k = 0; k < 4; k++) acc[i][j][k] = 0.f;

#pragma unroll
        for (int kk = 0; kk < 8; kk++) {
            int ks = kk * 16;
            uint32_t af[2][4];
#pragma unroll
            for (int mf = 0; mf < 2; mf++) {
                int mr = wm * 32 + mf * 16 + (lane & 7) + ((lane >> 3) & 1) * 8;
                int mc = ks + (lane >> 4) * 8;
                ldmx4(af[mf][0], af[mf][1], af[mf][2], af[mf][3], &Qs[mr * QK_STRIDE + mc]);
            }
            uint32_t bf[6][2];
#pragma unroll
            for (int np = 0; np < 3; np++) {
                int nr = p * 96 + wn * 48 + np * 16 + (lane & 7) + ((lane >> 4) ? 8 : 0);
                int nc = ks + (((lane >> 3) & 1) ? 8 : 0);
                ldmx4(bf[2 * np][0], bf[2 * np][1], bf[2 * np + 1][0], bf[2 * np + 1][1],
                      &Ks[nr * QK_STRIDE + nc]);
            }
#pragma unroll
            for (int mf = 0; mf < 2; mf++)
#pragma unroll
                for (int nf = 0; nf < 6; nf++) mma16816(acc[mf][nf], af[mf], bf[nf]);
        }
#pragma unroll
        for (int mf = 0; mf < 2; mf++) {
#pragma unroll
            for (int rh = 0; rh < 2; rh++) {
                int r = wm * 32 + mf * 16 + (lane >> 2) + rh * 8;
                float s = 0.f;
#pragma unroll
                for (int nf = 0; nf < 6; nf++) {
                    int col = p * 96 + wn * 48 + nf * 8 + 2 * (lane & 3);
                    float v0 = (col < KVLEN) ? __expf(acc[mf][nf][rh * 2 + 0] * SCALE) : 0.f;
                    float v1 = (col + 1 < KVLEN) ? __expf(acc[mf][nf][rh * 2 + 1] * SCALE) : 0.f;
                    *(__half2*)&Ps[r * PS_STRIDE + col] = __floats2half2_rn(v0, v1);
                    s += v0 + v1;
                }
                atomicAdd(&rowsum[r], s);
            }
        }
    }
    __syncthreads();
    // V replaces K (no normalization for V)
#pragma unroll
    for (int i = 0; i < 18; i++) {
        int idx = tid + 256 * i;
        int r = idx >> 4, c = (idx & 15) * 8;
        *(uint4*)&Ks[r * QK_STRIDE + c] = *(const uint4*)&g_Vh[(size_t)r * DIM + hc + c];
    }
    __syncthreads();

    float oc[2][8][4];
#pragma unroll
    for (int i = 0; i < 2; i++)
#pragma unroll
        for (int j = 0; j < 8; j++)
#pragma unroll
            for (int k = 0; k < 4; k++) oc[i][j][k] = 0.f;

    // 272 cols cover all nonzero P (257) rounded up to 16
    for (int kk = 0; kk < 17; kk++) {
        int ks = kk * 16;
        uint32_t af[2][4];
#pragma unroll
        for (int mf = 0; mf < 2; mf++) {
            int mr = wm * 32 + mf * 16 + (lane & 7) + ((lane >> 3) & 1) * 8;
            int mc = ks + (lane >> 4) * 8;
            ldmx4(af[mf][0], af[mf][1], af[mf][2], af[mf][3], &Ps[mr * PS_STRIDE + mc]);
        }
        uint32_t bf[8][2];
#pragma unroll
        for (int np = 0; np < 4; np++) {
            int vr = ks + (lane & 7) + ((lane >> 3) & 1) * 8;
            int vc = wn * 64 + np * 16 + (lane >> 4) * 8;
            ldmx4t(bf[2 * np][0], bf[2 * np][1], bf[2 * np + 1][0], bf[2 * np + 1][1],
                   &Ks[vr * QK_STRIDE + vc]);
        }
#pragma unroll
        for (int mf = 0; mf < 2; mf++)
#pragma unroll
            for (int nf = 0; nf < 8; nf++) mma16816(oc[mf][nf], af[mf], bf[nf]);
    }

#pragma unroll
    for (int mf = 0; mf < 2; mf++) {
#pragma unroll
        for (int rh = 0; rh < 2; rh++) {
            int r = wm * 32 + mf * 16 + (lane >> 2) + rh * 8;
            float inv = 1.0f / rowsum[r];
            size_t gro = (size_t)(m0 + r) * DIM + hc;
#pragma unroll
            for (int nf = 0; nf < 8; nf++) {
                int c = wn * 64 + nf * 8 + 2 * (lane & 3);
                *(float2*)&out[gro + c] =
                    make_float2(oc[mf][nf][rh * 2 + 0] * inv, oc[mf][nf][rh * 2 + 1] * inv);
            }
        }
    }
}

// ---------------- launcher ----------------
extern "C" void kernel_launch(void* const* d_in, const int* in_sizes, int n_in,
                              void* d_out, int out_size) {
    const float* hidden = (const float*)d_in[0];
    const float* enc = (const float*)d_in[1];
    const float* wq = (const float*)d_in[2];
    const float* bq = (const float*)d_in[3];
    const float* wk = (const float*)d_in[4];
    const float* bk = (const float*)d_in[5];
    const float* wv = (const float*)d_in[6];
    const float* bv = (const float*)d_in[7];
    const float* gq = (const float*)d_in[8];
    const float* gk = (const float*)d_in[9];
    float* out = (float*)d_out;

    void* p;
    cudaGetSymbolAddress(&p, g_Hh);    __half* Hh = (__half*)p;
    cudaGetSymbolAddress(&p, g_Eh);    __half* Eh = (__half*)p;
    cudaGetSymbolAddress(&p, g_Wqh);   __half* Wqh = (__half*)p;
    cudaGetSymbolAddress(&p, g_Wkh);   __half* Wkh = (__half*)p;
    cudaGetSymbolAddress(&p, g_Wvh);   __half* Wvh = (__half*)p;
    cudaGetSymbolAddress(&p, g_Qh);    __half* Qh = (__half*)p;
    cudaGetSymbolAddress(&p, g_Kh);    __half* Kh = (__half*)p;
    cudaGetSymbolAddress(&p, g_Vh);    __half* Vh = (__half*)p;
    cudaGetSymbolAddress(&p, g_ssq_q); float* ssq_q = (float*)p;
    cudaGetSymbolAddress(&p, g_ssq_k); float* ssq_k = (float*)p;

    // launch 0: H + Wq -> fp16, ssq zeroed
    k_prep_hwq<<<4096, 256>>>(hidden, wq);
    // launch 1: Wk, Wv, enc -> fp16
    k_prep_rest<<<2048, 256>>>(wk, wv, enc);
    // launch 2: K and V projections merged (one sub-wave launch)
    k_proj_kv<<<dim3(40, 3, 2), 256>>>(Eh, Wkh, Wvh, bk, bv, Kh, Vh, ssq_k);
    // launch 3: Q projection GEMM (ncu -s 5 lands here)
    k_proj_q<<<dim3(40, 128), 256>>>(Hh, Wqh, bq, Qh, ssq_q);
    // launch 4: attention with folded rmsnorm
    cudaFuncSetAttribute(k_attn, cudaFuncAttributeMaxDynamicSharedMemorySize, ATTN_SMEM);
    k_attn<<<dim3(128, NHEADS), 256, ATTN_SMEM>>>(gq, gk, out);
}

// round 7
// speedup vs baseline: 1.1995x; 1.0965x over previous
#include <cuda_runtime.h>
#include <cuda_fp16.h>
#include <stdint.h>

#define DIM    5120
#define SQ     16384
#define KVLEN  257
#define KVP    288
#define NHEADS 40
#define HDIM   128
#define INV_DIM (1.0f / 5120.0f)
#define RMS_EPS 1e-6f

// ---------------- scratch (device globals; no allocs allowed) ----------------
__device__ __half g_Hh  [(size_t)SQ * DIM];
__device__ __half g_Eh  [(size_t)KVLEN * DIM];
__device__ __half g_Wqh [(size_t)DIM * DIM];
__device__ __half g_Wkh [(size_t)DIM * DIM];
__device__ __half g_Wvh [(size_t)DIM * DIM];
__device__ __half g_Qh  [(size_t)SQ * DIM];    // raw q (pre-norm), fp16
__device__ __half g_Kh  [(size_t)KVP * DIM];   // raw k; rows >= 257 stay zero
__device__ __half g_Vh  [(size_t)KVP * DIM];   // v; rows >= 257 stay zero
__device__ float  g_ssq_q[SQ];
__device__ float  g_ssq_k[KVLEN];

// ---------------- helpers ----------------
__device__ __forceinline__ uint32_t smem_u32(const void* p) {
    return (uint32_t)__cvta_generic_to_shared(p);
}

__device__ __forceinline__ void ldmx4(uint32_t& r0, uint32_t& r1, uint32_t& r2, uint32_t& r3,
                                      const __half* p) {
    asm volatile("ldmatrix.sync.aligned.m8n8.x4.shared.b16 {%0,%1,%2,%3}, [%4];"
                 : "=r"(r0), "=r"(r1), "=r"(r2), "=r"(r3)
                 : "r"(smem_u32(p)));
}

__device__ __forceinline__ void ldmx4t(uint32_t& r0, uint32_t& r1, uint32_t& r2, uint32_t& r3,
                                       const __half* p) {
    asm volatile("ldmatrix.sync.aligned.m8n8.x4.trans.shared.b16 {%0,%1,%2,%3}, [%4];"
                 : "=r"(r0), "=r"(r1), "=r"(r2), "=r"(r3)
                 : "r"(smem_u32(p)));
}

__device__ __forceinline__ void mma16816(float* c, const uint32_t* a, const uint32_t* b) {
    asm volatile(
        "mma.sync.aligned.m16n8k16.row.col.f32.f16.f16.f32 "
        "{%0,%1,%2,%3},{%4,%5,%6,%7},{%8,%9},{%0,%1,%2,%3};"
        : "+f"(c[0]), "+f"(c[1]), "+f"(c[2]), "+f"(c[3])
        : "r"(a[0]), "r"(a[1]), "r"(a[2]), "r"(a[3]), "r"(b[0]), "r"(b[1]));
}

__device__ __forceinline__ void cp16(uint32_t dst, const void* src, bool pred) {
    asm volatile("cp.async.cg.shared.global [%0], [%1], 16, %2;"
                 :: "r"(dst), "l"(src), "r"(pred ? 16 : 0) : "memory");
}
#define CP_COMMIT() asm volatile("cp.async.commit_group;" ::: "memory")
#define CP_WAIT1()  asm volatile("cp.async.wait_group 1;" ::: "memory")

// ---------------- prep kernels ----------------
// launch 0: convert H + Wq to fp16, zero ssq arrays (everything gemm_q needs)
__global__ void k_prep_hwq(const float* __restrict__ H, const float* __restrict__ Wq) {
    const size_t PH = (size_t)SQ * DIM / 2;
    const size_t PW = (size_t)DIM * DIM / 2;
    size_t i0 = (size_t)blockIdx.x * blockDim.x + threadIdx.x;
    size_t st = (size_t)gridDim.x * blockDim.x;
    if (i0 < SQ) g_ssq_q[i0] = 0.f;
    if (i0 < KVLEN) g_ssq_k[i0] = 0.f;
    for (size_t i = i0; i < PH + PW; i += st) {
        if (i < PH) {
            float2 v = ((const float2*)H)[i];
            ((__half2*)g_Hh)[i] = __floats2half2_rn(v.x, v.y);
        } else {
            float2 v = ((const float2*)Wq)[i - PH];
            ((__half2*)g_Wqh)[i - PH] = __floats2half2_rn(v.x, v.y);
        }
    }
}

// launch 1: convert Wk, Wv, enc
__global__ void k_prep_rest(const float* __restrict__ Wk, const float* __restrict__ Wv,
                            const float* __restrict__ E) {
    const size_t PW = (size_t)DIM * DIM / 2;
    const size_t PE = (size_t)KVLEN * DIM / 2;
    size_t i0 = (size_t)blockIdx.x * blockDim.x + threadIdx.x;
    size_t st = (size_t)gridDim.x * blockDim.x;
    for (size_t i = i0; i < 2 * PW + PE; i += st) {
        if (i < PW) {
            float2 v = ((const float2*)Wk)[i];
            ((__half2*)g_Wkh)[i] = __floats2half2_rn(v.x, v.y);
        } else if (i < 2 * PW) {
            float2 v = ((const float2*)Wv)[i - PW];
            ((__half2*)g_Wvh)[i - PW] = __floats2half2_rn(v.x, v.y);
        } else {
            float2 v = ((const float2*)E)[i - 2 * PW];
            ((__half2*)g_Eh)[i - 2 * PW] = __floats2half2_rn(v.x, v.y);
        }
    }
}

// ---------------- projection GEMM core ----------------
// 128 threads = 4 warps (2m x 2n), warp tile 64x64; CTA tile 128x128, BK=32.
// 3-stage cp.async pipeline. out = fp16(A*W^T + bias); optional row ssq atomics.
#define P_STAGE  10240                   // halves per stage: A 128*40 + B 128*40
#define P_SMEM   (3 * P_STAGE * 2)       // 61440 bytes
#define P_NIT    (DIM / 32)              // 160

__device__ __forceinline__
void proj_body(const __half* __restrict__ A, const __half* __restrict__ W,
               const float* __restrict__ bias, int M,
               __half* __restrict__ out, float* __restrict__ ssq,
               int m0, int n0, __half* smh) {
    const int tid = threadIdx.x, lane = tid & 31, wid = tid >> 5;
    const int wm = wid & 1, wn = wid >> 1;

    auto load_stage = [&](int s) {
        const int kk = s * 32;
        __half* st = smh + (s % 3) * P_STAGE;
#pragma unroll
        for (int j = 0; j < 4; j++) {        // A: 512 x 16B chunks
            int ch = tid + j * 128;
            int r = ch >> 2, c16 = ch & 3;
            int row = m0 + r;
            bool ok = row < M;
            cp16(smem_u32(&st[r * 40 + c16 * 8]),
                 A + (size_t)(ok ? row : 0) * DIM + kk + c16 * 8, ok);
        }
        __half* bt = st + 5120;
#pragma unroll
        for (int j = 0; j < 4; j++) {        // B: 512 x 16B chunks
            int ch = tid + j * 128;
            int r = ch >> 2, c16 = ch & 3;
            cp16(smem_u32(&bt[r * 40 + c16 * 8]),
                 W + (size_t)(n0 + r) * DIM + kk + c16 * 8, true);
        }
        CP_COMMIT();
    };

    float acc[4][8][4];
#pragma unroll
    for (int i = 0; i < 4; i++)
#pragma unroll
        for (int j = 0; j < 8; j++)
#pragma unroll
            for (int k = 0; k < 4; k++) acc[i][j][k] = 0.f;

    load_stage(0);
    load_stage(1);

    for (int i = 0; i < P_NIT; i++) {
        CP_WAIT1();          // stage i resident
        __syncthreads();     // all warps done reading buffer (i-1)%3 == (i+2)%3
        if (i + 2 < P_NIT) load_stage(i + 2);
        else CP_COMMIT();    // empty group keeps wait count uniform

        const __half* a_s = smh + (i % 3) * P_STAGE;
        const __half* b_s = a_s + 5120;

#pragma unroll
        for (int ks = 0; ks < 32; ks += 16) {
            uint32_t af[4][4];
#pragma unroll
            for (int mf = 0; mf < 4; mf++) {
                int mr = wm * 64 + mf * 16 + (lane & 7) + ((lane >> 3) & 1) * 8;
                int mc = ks + (lane >> 4) * 8;
                ldmx4(af[mf][0], af[mf][1], af[mf][2], af[mf][3], &a_s[mr * 40 + mc]);
            }
#pragma unroll
            for (int np = 0; np < 4; np++) {   // B fragments consumed in place (low reg pressure)
                uint32_t b0[2], b1[2];
                int nr = wn * 64 + np * 16 + (lane & 7) + ((lane >> 4) ? 8 : 0);
                int nc = ks + (((lane >> 3) & 1) ? 8 : 0);
                ldmx4(b0[0], b0[1], b1[0], b1[1], &b_s[nr * 40 + nc]);
#pragma unroll
                for (int mf = 0; mf < 4; mf++) {
                    mma16816(acc[mf][2 * np + 0], af[mf], b0);
                    mma16816(acc[mf][2 * np + 1], af[mf], b1);
                }
            }
        }
    }

    // epilogue: fp16 store (+ optional row sum-of-squares)
#pragma unroll
    for (int mf = 0; mf < 4; mf++) {
#pragma unroll
        for (int rh = 0; rh < 2; rh++) {
            int gr = m0 + wm * 64 + mf * 16 + (lane >> 2) + rh * 8;
            if (gr >= M) continue;
            float s = 0.f;
#pragma unroll
            for (int nf = 0; nf < 8; nf++) {
                int gc = n0 + wn * 64 + nf * 8 + 2 * (lane & 3);
                float v0 = acc[mf][nf][rh * 2 + 0] + bias[gc];
                float v1 = acc[mf][nf][rh * 2 + 1] + bias[gc + 1];
                s += v0 * v0 + v1 * v1;
                *(__half2*)&out[(size_t)gr * DIM + gc] = __floats2half2_rn(v0, v1);
            }
            if (ssq) atomicAdd(&ssq[gr], s);
        }
    }
}

// Q projection (3 CTAs/SM target)
__global__ __launch_bounds__(128, 3)
void k_proj_q(const __half* __restrict__ A, const __half* __restrict__ W,
              const float* __restrict__ bias, __half* __restrict__ out,
              float* __restrict__ ssq) {
    extern __shared__ __align__(16) __half smh[];
    proj_body(A, W, bias, SQ, out, ssq, blockIdx.y * 128, blockIdx.x * 128, smh);
}

// K and V projections merged: z=0 -> K (with ssq), z=1 -> V
__global__ __launch_bounds__(128, 3)
void k_proj_kv(const __half* __restrict__ E,
               const __half* __restrict__ Wk, const __half* __restrict__ Wv,
               const float* __restrict__ bk, const float* __restrict__ bv,
               __half* __restrict__ Kh, __half* __restrict__ Vh,
               float* __restrict__ ssq_k) {
    extern __shared__ __align__(16) __half smh[];
    if (blockIdx.z == 0)
        proj_body(E, Wk, bk, KVLEN, Kh, ssq_k, blockIdx.y * 128, blockIdx.x * 128, smh);
    else
        proj_body(E, Wv, bv, KVLEN, Vh, (float*)0, blockIdx.y * 128, blockIdx.x * 128, smh);
}

// ---------------- fused attention (+ folded rmsnorm of Q and K) ----------------
#define QK_STRIDE 136
#define PS_STRIDE 296
#define SMEM_QS   0
#define SMEM_KS   34816
#define SMEM_PS   (34816 + 78336)
#define SMEM_RS   (34816 + 78336 + 75776)
#define ATTN_SMEM (34816 + 78336 + 75776 + 512)

__global__ __launch_bounds__(256, 1)
void k_attn(const float* __restrict__ gq, const float* __restrict__ gk,
            float* __restrict__ out) {
    extern __shared__ __align__(16) char smem[];
    __half* Qs = (__half*)(smem + SMEM_QS);
    __half* Ks = (__half*)(smem + SMEM_KS);  // reused for V in phase 2
    __half* Ps = (__half*)(smem + SMEM_PS);
    float* rowsum = (float*)(smem + SMEM_RS);

    const int tid = threadIdx.x, lane = tid & 31, wid = tid >> 5;
    const int wm = wid & 3, wn = wid >> 2;
    const int m0 = blockIdx.x * 128;
    const int h = blockIdx.y;
    const size_t hc = (size_t)h * HDIM;

    if (tid < 128) rowsum[tid] = 0.f;

    // Q tile 128x128: raw fp16 * rsqrt(ssq/D+eps) * g
#pragma unroll
    for (int i = 0; i < 8; i++) {
        int idx = tid + 256 * i;
        int r = idx >> 4, c = (idx & 15) * 8;
        float sc = rsqrtf(g_ssq_q[m0 + r] * INV_DIM + RMS_EPS);
        uint4 v = *(const uint4*)&g_Qh[(size_t)(m0 + r) * DIM + hc + c];
        __half2* hv = (__half2*)&v;
        const float2* gp = (const float2*)(gq + hc + c);
#pragma unroll
        for (int j = 0; j < 4; j++) {
            float2 f = __half22float2(hv[j]);
            float2 g2 = gp[j];
            hv[j] = __floats2half2_rn(f.x * sc * g2.x, f.y * sc * g2.y);
        }
        *(uint4*)&Qs[r * QK_STRIDE + c] = v;
    }
    // K tile 288x128: raw fp16 (rows>=257 are zero) * scale * g
#pragma unroll
    for (int i = 0; i < 18; i++) {
        int idx = tid + 256 * i;
        int r = idx >> 4, c = (idx & 15) * 8;
        int rr = r < KVLEN ? r : KVLEN - 1;
        float sc = rsqrtf(g_ssq_k[rr] * INV_DIM + RMS_EPS);
        uint4 v = *(const uint4*)&g_Kh[(size_t)r * DIM + hc + c];
        __half2* hv = (__half2*)&v;
        const float2* gp = (const float2*)(gk + hc + c);
#pragma unroll
        for (int j = 0; j < 4; j++) {
            float2 f = __half22float2(hv[j]);
            float2 g2 = gp[j];
            hv[j] = __floats2half2_rn(f.x * sc * g2.x, f.y * sc * g2.y);
        }
        *(uint4*)&Ks[r * QK_STRIDE + c] = v;
    }
    __syncthreads();

    const float SCALE = 0.088388347648318447f;  // 1/sqrt(128)
    for (int p = 0; p < 3; p++) {
        float acc[2][6][4];
#pragma unroll
        for (int i = 0; i < 2; i++)
#pragma unroll
            for (int j = 0; j < 6; j++)
#pragma unroll
                for (int k = 0; k < 4; k++) acc[i][j][k] = 0.f;

#pragma unroll
        for (int kk = 0; kk < 8; kk++) {
            int ks = kk * 16;
            uint32_t af[2][4];
#pragma unroll
            for (int mf = 0; mf < 2; mf++) {
                int mr = wm * 32 + mf * 16 + (lane & 7) + ((lane >> 3) & 1) * 8;
                int mc = ks + (lane >> 4) * 8;
                ldmx4(af[mf][0], af[mf][1], af[mf][2], af[mf][3], &Qs[mr * QK_STRIDE + mc]);
            }
            uint32_t bf[6][2];
#pragma unroll
            for (int np = 0; np < 3; np++) {
                int nr = p * 96 + wn * 48 + np * 16 + (lane & 7) + ((lane >> 4) ? 8 : 0);
                int nc = ks + (((lane >> 3) & 1) ? 8 : 0);
                ldmx4(bf[2 * np][0], bf[2 * np][1], bf[2 * np + 1][0], bf[2 * np + 1][1],
                      &Ks[nr * QK_STRIDE + nc]);
            }
#pragma unroll
            for (int mf = 0; mf < 2; mf++)
#pragma unroll
                for (int nf = 0; nf < 6; nf++) mma16816(acc[mf][nf], af[mf], bf[nf]);
        }
#pragma unroll
        for (int mf = 0; mf < 2; mf++) {
#pragma unroll
            for (int rh = 0; rh < 2; rh++) {
                int r = wm * 32 + mf * 16 + (lane >> 2) + rh * 8;
                float s = 0.f;
#pragma unroll
                for (int nf = 0; nf < 6; nf++) {
                    int col = p * 96 + wn * 48 + nf * 8 + 2 * (lane & 3);
                    float v0 = (col < KVLEN) ? __expf(acc[mf][nf][rh * 2 + 0] * SCALE) : 0.f;
                    float v1 = (col + 1 < KVLEN) ? __expf(acc[mf][nf][rh * 2 + 1] * SCALE) : 0.f;
                    *(__half2*)&Ps[r * PS_STRIDE + col] = __floats2half2_rn(v0, v1);
                    s += v0 + v1;
                }
                atomicAdd(&rowsum[r], s);
            }
        }
    }
    __syncthreads();
    // V replaces K (no normalization for V)
#pragma unroll
    for (int i = 0; i < 18; i++) {
        int idx = tid + 256 * i;
        int r = idx >> 4, c = (idx & 15) * 8;
        *(uint4*)&Ks[r * QK_STRIDE + c] = *(const uint4*)&g_Vh[(size_t)r * DIM + hc + c];
    }
    __syncthreads();

    float oc[2][8][4];
#pragma unroll
    for (int i = 0; i < 2; i++)
#pragma unroll
        for (int j = 0; j < 8; j++)
#pragma unroll
            for (int k = 0; k < 4; k++) oc[i][j][k] = 0.f;

    // 272 cols cover all nonzero P (257) rounded up to 16
    for (int kk = 0; kk < 17; kk++) {
        int ks = kk * 16;
        uint32_t af[2][4];
#pragma unroll
        for (int mf = 0; mf < 2; mf++) {
            int mr = wm * 32 + mf * 16 + (lane & 7) + ((lane >> 3) & 1) * 8;
            int mc = ks + (lane >> 4) * 8;
            ldmx4(af[mf][0], af[mf][1], af[mf][2], af[mf][3], &Ps[mr * PS_STRIDE + mc]);
        }
        uint32_t bf[8][2];
#pragma unroll
        for (int np = 0; np < 4; np++) {
            int vr = ks + (lane & 7) + ((lane >> 3) & 1) * 8;
            int vc = wn * 64 + np * 16 + (lane >> 4) * 8;
            ldmx4t(bf[2 * np][0], bf[2 * np][1], bf[2 * np + 1][0], bf[2 * np + 1][1],
                   &Ks[vr * QK_STRIDE + vc]);
        }
#pragma unroll
        for (int mf = 0; mf < 2; mf++)
#pragma unroll
            for (int nf = 0; nf < 8; nf++) mma16816(oc[mf][nf], af[mf], bf[nf]);
    }

#pragma unroll
    for (int mf = 0; mf < 2; mf++) {
#pragma unroll
        for (int rh = 0; rh < 2; rh++) {
            int r = wm * 32 + mf * 16 + (lane >> 2) + rh * 8;
            float inv = 1.0f / rowsum[r];
            size_t gro = (size_t)(m0 + r) * DIM + hc;
#pragma unroll
            for (int nf = 0; nf < 8; nf++) {
                int c = wn * 64 + nf * 8 + 2 * (lane & 3);
                *(float2*)&out[gro + c] =
                    make_float2(oc[mf][nf][rh * 2 + 0] * inv, oc[mf][nf][rh * 2 + 1] * inv);
            }
        }
    }
}

// ---------------- launcher ----------------
extern "C" void kernel_launch(void* const* d_in, const int* in_sizes, int n_in,
                              void* d_out, int out_size) {
    const float* hidden = (const float*)d_in[0];
    const float* enc = (const float*)d_in[1];
    const float* wq = (const float*)d_in[2];
    const float* bq = (const float*)d_in[3];
    const float* wk = (const float*)d_in[4];
    const float* bk = (const float*)d_in[5];
    const float* wv = (const float*)d_in[6];
    const float* bv = (const float*)d_in[7];
    const float* gq = (const float*)d_in[8];
    const float* gk = (const float*)d_in[9];
    float* out = (float*)d_out;

    void* p;
    cudaGetSymbolAddress(&p, g_Hh);    __half* Hh = (__half*)p;
    cudaGetSymbolAddress(&p, g_Eh);    __half* Eh = (__half*)p;
    cudaGetSymbolAddress(&p, g_Wqh);   __half* Wqh = (__half*)p;
    cudaGetSymbolAddress(&p, g_Wkh);   __half* Wkh = (__half*)p;
    cudaGetSymbolAddress(&p, g_Wvh);   __half* Wvh = (__half*)p;
    cudaGetSymbolAddress(&p, g_Qh);    __half* Qh = (__half*)p;
    cudaGetSymbolAddress(&p, g_Kh);    __half* Kh = (__half*)p;
    cudaGetSymbolAddress(&p, g_Vh);    __half* Vh = (__half*)p;
    cudaGetSymbolAddress(&p, g_ssq_q); float* ssq_q = (float*)p;
    cudaGetSymbolAddress(&p, g_ssq_k); float* ssq_k = (float*)p;

    // launch 0: H + Wq -> fp16, ssq zeroed
    k_prep_hwq<<<4096, 256>>>(hidden, wq);
    // launch 1: Wk, Wv, enc -> fp16
    k_prep_rest<<<2048, 256>>>(wk, wv, enc);
    // launch 2: K and V projections merged
    cudaFuncSetAttribute(k_proj_kv, cudaFuncAttributeMaxDynamicSharedMemorySize, P_SMEM);
    k_proj_kv<<<dim3(40, 3, 2), 128, P_SMEM>>>(Eh, Wkh, Wvh, bk, bv, Kh, Vh, ssq_k);
    // launch 3: Q projection GEMM (ncu profiles this slot)
    cudaFuncSetAttribute(k_proj_q, cudaFuncAttributeMaxDynamicSharedMemorySize, P_SMEM);
    k_proj_q<<<dim3(40, 128), 128, P_SMEM>>>(Hh, Wqh, bq, Qh, ssq_q);
    // launch 4: attention with folded rmsnorm
    cudaFuncSetAttribute(k_attn, cudaFuncAttributeMaxDynamicSharedMemorySize, ATTN_SMEM);
    k_attn<<<dim3(128, NHEADS), 256, ATTN_SMEM>>>(gq, gk, out);
}